// round 10
// baseline (speedup 1.0000x reference)
#include <cuda_runtime.h>
#include <cstdint>

#define FLT_MAX_ 3.402823466e+38f

// Problem constants
#define BGR 512
#define NPG 256
#define EDG 1048576
#define EPG 2048          // edges per graph (edge array is grouped by graph)
#define HF  128
#define K1  205
#define K2  164
#define K3  132
#define M1  (BGR*NPG)   // 131072
#define M2  (BGR*K1)    // 104960
#define M3  (BGR*K2)    // 83968

// ---------------- XLA/Eigen fp32 tanh (generic_fast_tanh_float) ----------------
// Bit-replicates the approximation XLA lowers jnp.tanh(f32) to on CPU and GPU:
// clamp to +-7.90531110763549805, identity below 4e-4, rational P(x^2)*x / Q(x^2),
// all in fp32 with FMA. Intrinsics pin rounding against --use_fast_math.
__device__ __forceinline__ float xla_tanh(float x) {
    const float ax = fabsf(x);
    float xc = fminf(fmaxf(x, -7.90531110763549805f), 7.90531110763549805f);
    float x2 = __fmul_rn(xc, xc);
    float p = __fmaf_rn(x2, -2.76076847742355e-16f, 2.00018790482477e-13f); // a13,a11
    p = __fmaf_rn(x2, p, -8.60467152213735e-11f);  // a9
    p = __fmaf_rn(x2, p,  5.12229709037114e-08f);  // a7
    p = __fmaf_rn(x2, p,  1.48572235717979e-05f);  // a5
    p = __fmaf_rn(x2, p,  6.37261928875436e-04f);  // a3
    p = __fmaf_rn(x2, p,  4.89352455891786e-03f);  // a1
    p = __fmul_rn(xc, p);
    float q = __fmaf_rn(x2, 1.19825839466702e-06f, 1.18534705686654e-04f);  // b6,b4
    q = __fmaf_rn(x2, q, 2.26843463243900e-03f);   // b2
    q = __fmaf_rn(x2, q, 4.89352518554385e-03f);   // b0
    return (ax < 0.0004f) ? xc : __fdiv_rn(p, q);
}

// ---------------- scratch (device globals; no allocation allowed) ----------------
__device__ __align__(16) float g_agg[M1 * HF];      // reused each layer
__device__ __align__(16) float g_h1 [M1 * HF];
__device__ __align__(16) float g_hp1[M2 * HF];
__device__ __align__(16) float g_h2 [M2 * HF];
__device__ __align__(16) float g_hp2[M3 * HF];
__device__ __align__(16) float g_h3 [M3 * HF];
__device__ __align__(16) float g_hp3[BGR * K3 * HF];
__device__ int   g_mapA[M1];     // orig node -> pooled1 id or -1
__device__ int   g_mapB[M2];     // pooled1 id -> pooled2 id or -1
__device__ __align__(16) float g_z[BGR * 2 * HF];   // readout accumulator [512,256]

// ---------------- deterministic per-graph aggregation (exact fp32) ----------------
__global__ __launch_bounds__(256) void agg_kernel(
    const float* __restrict__ xin,
    const int* __restrict__ src, const int* __restrict__ dst,
    const int* __restrict__ map1, const int* __restrict__ map2,
    float* __restrict__ agg, int n_per)
{
    __shared__ int cnt[256];
    __shared__ int sc[256];
    __shared__ int offs[256];
    __shared__ int cur[256];
    __shared__ unsigned int elist[EPG];   // (e_local << 8) | s_local

    const int g = blockIdx.x, tid = threadIdx.x;
    cnt[tid] = 0;
    __syncthreads();

    int dl[8]; unsigned int pk[8];
#pragma unroll
    for (int i = 0; i < 8; i++) {
        const int el = tid + i * 256;
        const int e  = g * EPG + el;
        int s = __ldg(src + e);
        int d = __ldg(dst + e);
        bool ok = true;
        if (map1) { s = __ldg(map1 + s); d = __ldg(map1 + d); ok = ((s | d) >= 0); }
        if (ok && map2) { s = __ldg(map2 + s); d = __ldg(map2 + d); ok = ((s | d) >= 0); }
        if (ok) {
            const int dd = d - g * n_per;
            const int ss = s - g * n_per;
            dl[i] = dd;
            pk[i] = ((unsigned)el << 8) | (unsigned)ss;
            atomicAdd(&cnt[dd], 1);
        } else dl[i] = -1;
    }
    __syncthreads();

    sc[tid] = cnt[tid];
    __syncthreads();
    for (int st = 1; st < 256; st <<= 1) {
        int add = (tid >= st) ? sc[tid - st] : 0;
        __syncthreads();
        sc[tid] += add;
        __syncthreads();
    }
    offs[tid] = sc[tid] - cnt[tid];
    cur[tid]  = offs[tid];
    __syncthreads();

#pragma unroll
    for (int i = 0; i < 8; i++) {
        if (dl[i] >= 0) {
            int slot = atomicAdd(&cur[dl[i]], 1);
            elist[slot] = pk[i];
        }
    }
    __syncthreads();

    {
        const int beg = offs[tid], n = cnt[tid];
        for (int a = 1; a < n; a++) {
            unsigned int key = elist[beg + a];
            int b = a - 1;
            while (b >= 0 && elist[beg + b] > key) { elist[beg + b + 1] = elist[beg + b]; b--; }
            elist[beg + b + 1] = key;
        }
    }
    __syncthreads();

    const int warp = tid >> 5, lane = tid & 31;
    const float4* xg = reinterpret_cast<const float4*>(xin) + (size_t)g * n_per * 32;
    float4* av = reinterpret_cast<float4*>(agg) + (size_t)g * n_per * 32;
    for (int d = warp; d < n_per; d += 8) {
        const int beg = offs[d], n = cnt[d];
        float4 a = make_float4(0.f, 0.f, 0.f, 0.f);
        for (int j = 0; j < n; j++) {
            const int sl = (int)(elist[beg + j] & 255u);
            float4 v = __ldg(xg + (size_t)sl * 32 + lane);
            a.x += v.x; a.y += v.y; a.z += v.z; a.w += v.w;
        }
        av[(size_t)d * 32 + lane] = a;
    }
}

// ---------------- fused conv GEMM: out = relu((A1@B1 + bias) + A2@B2) ----------------
// High-accuracy accumulation: 8-term tile partials (FFMA) folded into the main
// accumulator with Kahan compensation every k-tile. Reduces sequential-sum error
// ~10x so the residual vs the reference is dominated by the reference's own
// accumulation-order noise.
__global__ __launch_bounds__(256) void gemm_conv(
    const float* __restrict__ A1, const float* __restrict__ A2,
    const float* __restrict__ B1, const float* __restrict__ B2,
    const float* __restrict__ bias, float* __restrict__ out, int M)
{
    __shared__ float As[8][128];
    __shared__ float Bs[8][128];
    const int tid = threadIdx.x;
    const int row0 = blockIdx.x * 128;
    const int tx = tid & 15, ty = tid >> 4;
    const int lm = tid >> 1;
    const int lk = (tid & 1) * 4;
    const int bk = tid >> 5;
    const int bn = (tid & 31) * 4;

    float acc[8][8], comp[8][8], part[8][8];
#pragma unroll
    for (int i = 0; i < 8; i++)
#pragma unroll
        for (int j = 0; j < 8; j++) { acc[i][j] = 0.f; comp[i][j] = 0.f; part[i][j] = 0.f; }

    float bb[8];
#pragma unroll
    for (int j = 0; j < 8; j++) bb[j] = __ldg(bias + tx * 8 + j);

#pragma unroll 1
    for (int kk = 0; kk < 32; ++kk) {
        const float* Asrc = (kk < 16) ? A1 : A2;
        const float* Bsrc = (kk < 16) ? B1 : B2;
        const int koff = (kk & 15) * 8;
        float4 avv = *reinterpret_cast<const float4*>(Asrc + (size_t)(row0 + lm) * 128 + koff + lk);
        float4 bvv = *reinterpret_cast<const float4*>(Bsrc + (size_t)(koff + bk) * 128 + bn);
        __syncthreads();
        As[lk + 0][lm] = avv.x; As[lk + 1][lm] = avv.y;
        As[lk + 2][lm] = avv.z; As[lk + 3][lm] = avv.w;
        *reinterpret_cast<float4*>(&Bs[bk][bn]) = bvv;
        __syncthreads();
#pragma unroll
        for (int k = 0; k < 8; ++k) {
            float a[8], b[8];
            *reinterpret_cast<float4*>(a)     = *reinterpret_cast<const float4*>(&As[k][ty * 8]);
            *reinterpret_cast<float4*>(a + 4) = *reinterpret_cast<const float4*>(&As[k][ty * 8 + 4]);
            *reinterpret_cast<float4*>(b)     = *reinterpret_cast<const float4*>(&Bs[k][tx * 8]);
            *reinterpret_cast<float4*>(b + 4) = *reinterpret_cast<const float4*>(&Bs[k][tx * 8 + 4]);
#pragma unroll
            for (int i = 0; i < 8; i++)
#pragma unroll
                for (int j = 0; j < 8; j++) part[i][j] = __fmaf_rn(a[i], b[j], part[i][j]);
        }
        // Kahan-fold the 8-term tile partial into acc, reset partial
#pragma unroll
        for (int i = 0; i < 8; i++)
#pragma unroll
            for (int j = 0; j < 8; j++) {
                float y = __fsub_rn(part[i][j], comp[i][j]);
                float t = __fadd_rn(acc[i][j], y);
                comp[i][j] = __fsub_rn(__fsub_rn(t, acc[i][j]), y);
                acc[i][j] = t;
                part[i][j] = 0.f;
            }
        if (kk == 15) {
            // bias between the two halves: matches reference add order
#pragma unroll
            for (int i = 0; i < 8; i++)
#pragma unroll
                for (int j = 0; j < 8; j++) acc[i][j] = __fadd_rn(acc[i][j], bb[j]);
        }
    }

#pragma unroll
    for (int i = 0; i < 8; i++) {
        int m = row0 + ty * 8 + i;
#pragma unroll
        for (int j = 0; j < 8; j += 4) {
            float4 o;
            o.x = fmaxf(__fsub_rn(acc[i][j + 0], comp[i][j + 0]), 0.f);
            o.y = fmaxf(__fsub_rn(acc[i][j + 1], comp[i][j + 1]), 0.f);
            o.z = fmaxf(__fsub_rn(acc[i][j + 2], comp[i][j + 2]), 0.f);
            o.w = fmaxf(__fsub_rn(acc[i][j + 3], comp[i][j + 3]), 0.f);
            *reinterpret_cast<float4*>(out + (size_t)m * 128 + tx * 8 + j) = o;
        }
    }
}

// ---------------- TopK pool: per-graph block (256 threads) ----------------
// Score path replicates XLA fp32 semantics: fp32 dot, fp32 norm (sqrt.rn),
// fp32 div (rn), XLA rational tanh.
__global__ __launch_bounds__(256) void pool_kernel(
    const float* __restrict__ h, const float* __restrict__ p,
    float* __restrict__ hp, int* __restrict__ map_out,
    int n_per, int k)
{
    __shared__ float ps[128];
    __shared__ float ss[256];
    __shared__ int   si[256];
    __shared__ float s_norm;
    const int b = blockIdx.x, tid = threadIdx.x;

    if (tid < 128) ps[tid] = p[tid];
    __syncthreads();
    if (tid < 32) {
        float v = ps[tid] * ps[tid] + ps[tid + 32] * ps[tid + 32]
                + ps[tid + 64] * ps[tid + 64] + ps[tid + 96] * ps[tid + 96];
#pragma unroll
        for (int o = 16; o; o >>= 1) v += __shfl_xor_sync(0xffffffffu, v, o);
        if (tid == 0) s_norm = __fsqrt_rn(v);
    }
    __syncthreads();

    const int warp = tid >> 5, lane = tid & 31;
    for (int i = warp; i < 256; i += 8) {
        if (i < n_per) {
            const float* row = h + ((size_t)b * n_per + i) * 128;
            float d = row[lane] * ps[lane] + row[lane + 32] * ps[lane + 32]
                    + row[lane + 64] * ps[lane + 64] + row[lane + 96] * ps[lane + 96];
#pragma unroll
            for (int o = 16; o; o >>= 1) d += __shfl_xor_sync(0xffffffffu, d, o);
            if (lane == 0) {
                ss[i] = xla_tanh(__fdiv_rn(d, s_norm));
                si[i] = i;
            }
        } else if (lane == 0) { ss[i] = -FLT_MAX_; si[i] = i; }
    }
    __syncthreads();

    // Bitonic sort 256 entries: (score desc, idx asc) to match lax.top_k
    for (int ksz = 2; ksz <= 256; ksz <<= 1) {
        for (int j = ksz >> 1; j > 0; j >>= 1) {
            int i = tid, ixj = i ^ j;
            if (ixj > i) {
                float s_i = ss[i], s_x = ss[ixj];
                int   i_i = si[i], i_x = si[ixj];
                bool before = (s_i > s_x) || (s_i == s_x && i_i < i_x);
                bool up = ((i & ksz) == 0);
                if (up ? !before : before) {
                    ss[i] = s_x; ss[ixj] = s_i;
                    si[i] = i_x; si[ixj] = i_i;
                }
            }
            __syncthreads();
        }
    }

    if (map_out) {
        for (int i = tid; i < n_per; i += 256) map_out[b * n_per + i] = -1;
        __syncthreads();
        for (int r = tid; r < k; r += 256) map_out[b * n_per + si[r]] = b * k + r;
    }

    const int total = k * 128;
    for (int t = tid; t < total; t += 256) {
        int r = t >> 7, c = t & 127;
        hp[((size_t)b * k + r) * 128 + c] =
            __fmul_rn(h[((size_t)b * n_per + si[r]) * 128 + c], ss[r]);
    }
}

// ---------------- readout: z[b] (+)= [max over k ; mean over k] ----------------
__global__ __launch_bounds__(128) void readout_kernel(
    const float* __restrict__ hp, int k, float* __restrict__ z, int accumulate)
{
    const int b = blockIdx.x, f = threadIdx.x;
    float mx = -FLT_MAX_, sm = 0.f;
    const float* base = hp + (size_t)b * k * 128 + f;
    for (int r = 0; r < k; r++) {
        float v = base[(size_t)r * 128];
        mx = fmaxf(mx, v);
        sm += v;
    }
    float mean = __fdiv_rn(sm, (float)k);
    if (accumulate) {
        z[b * 256 + f]       += mx;
        z[b * 256 + 128 + f] += mean;
    } else {
        z[b * 256 + f]       = mx;
        z[b * 256 + 128 + f] = mean;
    }
}

// ---------------- MLP head + log_softmax (exact fp32 matmuls, double softmax) ----------------
__global__ __launch_bounds__(128) void mlp_kernel(
    const float* __restrict__ z,
    const float* __restrict__ wl1, const float* __restrict__ bl1,
    const float* __restrict__ wl2, const float* __restrict__ bl2,
    const float* __restrict__ wl3, const float* __restrict__ bl3,
    float* __restrict__ out)
{
    __shared__ float zr[256], t1[128], t2[64], lg[10];
    const int b = blockIdx.x, t = threadIdx.x;
    zr[t]       = z[b * 256 + t];
    zr[t + 128] = z[b * 256 + 128 + t];
    __syncthreads();
    float s = bl1[t];
    for (int k = 0; k < 256; k++) s = __fmaf_rn(zr[k], wl1[k * 128 + t], s);
    t1[t] = fmaxf(s, 0.f);
    __syncthreads();
    if (t < 64) {
        float s2 = bl2[t];
        for (int k = 0; k < 128; k++) s2 = __fmaf_rn(t1[k], wl2[k * 64 + t], s2);
        t2[t] = fmaxf(s2, 0.f);
    }
    __syncthreads();
    if (t < 10) {
        float s3 = bl3[t];
        for (int k = 0; k < 64; k++) s3 = __fmaf_rn(t2[k], wl3[k * 10 + t], s3);
        lg[t] = s3;
    }
    __syncthreads();
    if (t == 0) {
        float mx = -FLT_MAX_;
        for (int c = 0; c < 10; c++) mx = fmaxf(mx, lg[c]);
        double se = 0.0;
        for (int c = 0; c < 10; c++) se += exp((double)(lg[c] - mx));
        double lse = (double)mx + log(se);
        for (int c = 0; c < 10; c++) out[b * 10 + c] = (float)((double)lg[c] - lse);
    }
}

// ---------------- launch ----------------
extern "C" void kernel_launch(void* const* d_in, const int* in_sizes, int n_in,
                              void* d_out, int out_size)
{
    const float* x      = (const float*)d_in[0];
    const int*   src    = (const int*)  d_in[1];
    const int*   dst    = (const int*)  d_in[2];
    const float* w1_rel = (const float*)d_in[3];
    const float* w1_root= (const float*)d_in[4];
    const float* b1     = (const float*)d_in[5];
    const float* p1     = (const float*)d_in[6];
    const float* w2_rel = (const float*)d_in[7];
    const float* w2_root= (const float*)d_in[8];
    const float* b2     = (const float*)d_in[9];
    const float* p2     = (const float*)d_in[10];
    const float* w3_rel = (const float*)d_in[11];
    const float* w3_root= (const float*)d_in[12];
    const float* b3     = (const float*)d_in[13];
    const float* p3     = (const float*)d_in[14];
    const float* wl1    = (const float*)d_in[15];
    const float* bl1    = (const float*)d_in[16];
    const float* wl2    = (const float*)d_in[17];
    const float* bl2    = (const float*)d_in[18];
    const float* wl3    = (const float*)d_in[19];
    const float* bl3    = (const float*)d_in[20];
    float* out = (float*)d_out;

    float *agg, *h1, *hp1, *h2, *hp2, *h3, *hp3, *z;
    int *mapA, *mapB;
    cudaGetSymbolAddress((void**)&agg,  g_agg);
    cudaGetSymbolAddress((void**)&h1,   g_h1);
    cudaGetSymbolAddress((void**)&hp1,  g_hp1);
    cudaGetSymbolAddress((void**)&h2,   g_h2);
    cudaGetSymbolAddress((void**)&hp2,  g_hp2);
    cudaGetSymbolAddress((void**)&h3,   g_h3);
    cudaGetSymbolAddress((void**)&hp3,  g_hp3);
    cudaGetSymbolAddress((void**)&z,    g_z);
    cudaGetSymbolAddress((void**)&mapA, g_mapA);
    cudaGetSymbolAddress((void**)&mapB, g_mapB);

    // ---- layer 1 ----
    agg_kernel<<<BGR, 256>>>(x, src, dst, nullptr, nullptr, agg, NPG);
    gemm_conv<<<M1 / 128, 256>>>(agg, x, w1_rel, w1_root, b1, h1, M1);
    pool_kernel<<<BGR, 256>>>(h1, p1, hp1, mapA, NPG, K1);
    readout_kernel<<<BGR, 128>>>(hp1, K1, z, 0);

    // ---- layer 2 ----
    agg_kernel<<<BGR, 256>>>(hp1, src, dst, mapA, nullptr, agg, K1);
    gemm_conv<<<M2 / 128, 256>>>(agg, hp1, w2_rel, w2_root, b2, h2, M2);
    pool_kernel<<<BGR, 256>>>(h2, p2, hp2, mapB, K1, K2);
    readout_kernel<<<BGR, 128>>>(hp2, K2, z, 1);

    // ---- layer 3 ----
    agg_kernel<<<BGR, 256>>>(hp2, src, dst, mapA, mapB, agg, K2);
    gemm_conv<<<M3 / 128, 256>>>(agg, hp2, w3_rel, w3_root, b3, h3, M3);
    pool_kernel<<<BGR, 256>>>(h3, p3, hp3, nullptr, K2, K3);
    readout_kernel<<<BGR, 128>>>(hp3, K3, z, 1);

    // ---- head ----
    mlp_kernel<<<BGR, 128>>>(z, wl1, bl1, wl2, bl2, wl3, bl3, out);
}

// round 11
// speedup vs baseline: 1.0905x; 1.0905x over previous
#include <cuda_runtime.h>
#include <cstdint>

#define FLT_MAX_ 3.402823466e+38f

// Problem constants
#define BGR 512
#define NPG 256
#define EDG 1048576
#define EPG 2048          // edges per graph (edge array is grouped by graph)
#define HF  128
#define K1  205
#define K2  164
#define K3  132
#define M1  (BGR*NPG)   // 131072
#define M2  (BGR*K1)    // 104960
#define M3  (BGR*K2)    // 83968

// ---------------- XLA/Eigen fp32 tanh (generic_fast_tanh_float) ----------------
__device__ __forceinline__ float xla_tanh(float x) {
    const float ax = fabsf(x);
    float xc = fminf(fmaxf(x, -7.90531110763549805f), 7.90531110763549805f);
    float x2 = __fmul_rn(xc, xc);
    float p = __fmaf_rn(x2, -2.76076847742355e-16f, 2.00018790482477e-13f);
    p = __fmaf_rn(x2, p, -8.60467152213735e-11f);
    p = __fmaf_rn(x2, p,  5.12229709037114e-08f);
    p = __fmaf_rn(x2, p,  1.48572235717979e-05f);
    p = __fmaf_rn(x2, p,  6.37261928875436e-04f);
    p = __fmaf_rn(x2, p,  4.89352455891786e-03f);
    p = __fmul_rn(xc, p);
    float q = __fmaf_rn(x2, 1.19825839466702e-06f, 1.18534705686654e-04f);
    q = __fmaf_rn(x2, q, 2.26843463243900e-03f);
    q = __fmaf_rn(x2, q, 4.89352518554385e-03f);
    return (ax < 0.0004f) ? xc : __fdiv_rn(p, q);
}

// ---------------- scratch ----------------
__device__ __align__(16) float g_agg[M1 * HF];
__device__ __align__(16) float g_h1 [M1 * HF];
__device__ __align__(16) float g_hp1[M2 * HF];
__device__ __align__(16) float g_h2 [M2 * HF];
__device__ __align__(16) float g_hp2[M3 * HF];
__device__ __align__(16) float g_h3 [M3 * HF];
__device__ __align__(16) float g_hp3[BGR * K3 * HF];
__device__ int   g_mapA[M1];
__device__ int   g_mapB[M2];
__device__ __align__(16) float g_z[BGR * 2 * HF];

// ---------------- deterministic per-graph aggregation (exact fp32) ----------------
__global__ __launch_bounds__(256) void agg_kernel(
    const float* __restrict__ xin,
    const int* __restrict__ src, const int* __restrict__ dst,
    const int* __restrict__ map1, const int* __restrict__ map2,
    float* __restrict__ agg, int n_per)
{
    __shared__ int cnt[256];
    __shared__ int sc[256];
    __shared__ int offs[256];
    __shared__ int cur[256];
    __shared__ unsigned int elist[EPG];   // (e_local << 8) | s_local

    const int g = blockIdx.x, tid = threadIdx.x;
    cnt[tid] = 0;
    __syncthreads();

    int dl[8]; unsigned int pk[8];
#pragma unroll
    for (int i = 0; i < 8; i++) {
        const int el = tid + i * 256;
        const int e  = g * EPG + el;
        int s = __ldg(src + e);
        int d = __ldg(dst + e);
        bool ok = true;
        if (map1) { s = __ldg(map1 + s); d = __ldg(map1 + d); ok = ((s | d) >= 0); }
        if (ok && map2) { s = __ldg(map2 + s); d = __ldg(map2 + d); ok = ((s | d) >= 0); }
        if (ok) {
            const int dd = d - g * n_per;
            const int ss = s - g * n_per;
            dl[i] = dd;
            pk[i] = ((unsigned)el << 8) | (unsigned)ss;
            atomicAdd(&cnt[dd], 1);
        } else dl[i] = -1;
    }
    __syncthreads();

    sc[tid] = cnt[tid];
    __syncthreads();
    for (int st = 1; st < 256; st <<= 1) {
        int add = (tid >= st) ? sc[tid - st] : 0;
        __syncthreads();
        sc[tid] += add;
        __syncthreads();
    }
    offs[tid] = sc[tid] - cnt[tid];
    cur[tid]  = offs[tid];
    __syncthreads();

#pragma unroll
    for (int i = 0; i < 8; i++) {
        if (dl[i] >= 0) {
            int slot = atomicAdd(&cur[dl[i]], 1);
            elist[slot] = pk[i];
        }
    }
    __syncthreads();

    {
        const int beg = offs[tid], n = cnt[tid];
        for (int a = 1; a < n; a++) {
            unsigned int key = elist[beg + a];
            int b = a - 1;
            while (b >= 0 && elist[beg + b] > key) { elist[beg + b + 1] = elist[beg + b]; b--; }
            elist[beg + b + 1] = key;
        }
    }
    __syncthreads();

    const int warp = tid >> 5, lane = tid & 31;
    const float4* xg = reinterpret_cast<const float4*>(xin) + (size_t)g * n_per * 32;
    float4* av = reinterpret_cast<float4*>(agg) + (size_t)g * n_per * 32;
    for (int d = warp; d < n_per; d += 8) {
        const int beg = offs[d], n = cnt[d];
        float4 a = make_float4(0.f, 0.f, 0.f, 0.f);
        for (int j = 0; j < n; j++) {
            const int sl = (int)(elist[beg + j] & 255u);
            float4 v = __ldg(xg + (size_t)sl * 32 + lane);
            a.x += v.x; a.y += v.y; a.z += v.z; a.w += v.w;
        }
        av[(size_t)d * 32 + lane] = a;
    }
}

// ---------------- fused conv GEMM: out = relu((A1@B1 + bias) + A2@B2) ----------------
// 64x128 tile, 256 threads, 8Mx4N per thread. Double-buffered smem (1 sync/tile).
// Kahan-compensated accumulation: 16-term FFMA partials folded every 2 k-tiles.
// Accuracy class ~1e-7 (required: plain sequential fp32 fails the top-k boundaries).
__global__ __launch_bounds__(256) void gemm_conv(
    const float* __restrict__ A1, const float* __restrict__ A2,
    const float* __restrict__ B1, const float* __restrict__ B2,
    const float* __restrict__ bias, float* __restrict__ out, int M)
{
    __shared__ float As[2][8][68];    // padded: conflict-free transposed stores
    __shared__ float Bs[2][8][128];
    const int tid = threadIdx.x;
    const int row0 = blockIdx.x * 64;
    const int tx = tid & 31;          // N: 4 cols each (tx*4)
    const int ty = tid >> 5;          // M: 8 rows each (ty*8)
    const int arow = tid >> 2;        // A load: row 0..63
    const int akp  = (tid & 3) * 2;   // A load: k pair
    const int bk   = tid >> 5;        // B load: k row 0..7
    const int bcol = (tid & 31) * 4;  // B load: col

    float acc[8][4], comp[8][4], part[8][4];
#pragma unroll
    for (int i = 0; i < 8; i++)
#pragma unroll
        for (int j = 0; j < 4; j++) { acc[i][j] = 0.f; comp[i][j] = 0.f; part[i][j] = 0.f; }

    float bb[4];
#pragma unroll
    for (int j = 0; j < 4; j++) bb[j] = __ldg(bias + tx * 4 + j);

    // prefetch tile 0
    float2 pa = *reinterpret_cast<const float2*>(A1 + (size_t)(row0 + arow) * 128 + akp);
    float4 pb = *reinterpret_cast<const float4*>(B1 + (size_t)bk * 128 + bcol);
    As[0][akp][arow] = pa.x; As[0][akp + 1][arow] = pa.y;
    *reinterpret_cast<float4*>(&Bs[0][bk][bcol]) = pb;
    __syncthreads();

#pragma unroll 1
    for (int kk = 0; kk < 32; ++kk) {
        const int cur = kk & 1, nxt = cur ^ 1;
        if (kk < 31) {
            const int kn = kk + 1;
            const float* Asrc = (kn < 16) ? A1 : A2;
            const float* Bsrc = (kn < 16) ? B1 : B2;
            const int koff = (kn & 15) * 8;
            pa = *reinterpret_cast<const float2*>(Asrc + (size_t)(row0 + arow) * 128 + koff + akp);
            pb = *reinterpret_cast<const float4*>(Bsrc + (size_t)(koff + bk) * 128 + bcol);
        }
#pragma unroll
        for (int k = 0; k < 8; ++k) {
            float a[8], b[4];
            *reinterpret_cast<float4*>(a)     = *reinterpret_cast<const float4*>(&As[cur][k][ty * 8]);
            *reinterpret_cast<float4*>(a + 4) = *reinterpret_cast<const float4*>(&As[cur][k][ty * 8 + 4]);
            *reinterpret_cast<float4*>(b)     = *reinterpret_cast<const float4*>(&Bs[cur][k][tx * 4]);
#pragma unroll
            for (int i = 0; i < 8; i++)
#pragma unroll
                for (int j = 0; j < 4; j++) part[i][j] = __fmaf_rn(a[i], b[j], part[i][j]);
        }
        if (kk & 1) {
            // Kahan-fold 16-term partial into acc
#pragma unroll
            for (int i = 0; i < 8; i++)
#pragma unroll
                for (int j = 0; j < 4; j++) {
                    float y = __fsub_rn(part[i][j], comp[i][j]);
                    float t = __fadd_rn(acc[i][j], y);
                    comp[i][j] = __fsub_rn(__fsub_rn(t, acc[i][j]), y);
                    acc[i][j] = t;
                    part[i][j] = 0.f;
                }
            if (kk == 15) {
                // bias between the two K=128 halves (reference add order)
#pragma unroll
                for (int i = 0; i < 8; i++)
#pragma unroll
                    for (int j = 0; j < 4; j++) acc[i][j] = __fadd_rn(acc[i][j], bb[j]);
            }
        }
        if (kk < 31) {
            As[nxt][akp][arow] = pa.x; As[nxt][akp + 1][arow] = pa.y;
            *reinterpret_cast<float4*>(&Bs[nxt][bk][bcol]) = pb;
        }
        __syncthreads();
    }

#pragma unroll
    for (int i = 0; i < 8; i++) {
        const int m = row0 + ty * 8 + i;
        float4 o;
        o.x = fmaxf(__fsub_rn(acc[i][0], comp[i][0]), 0.f);
        o.y = fmaxf(__fsub_rn(acc[i][1], comp[i][1]), 0.f);
        o.z = fmaxf(__fsub_rn(acc[i][2], comp[i][2]), 0.f);
        o.w = fmaxf(__fsub_rn(acc[i][3], comp[i][3]), 0.f);
        *reinterpret_cast<float4*>(out + (size_t)m * 128 + tx * 4) = o;
    }
}

// ---------------- TopK pool + fused readout: per-graph block (256 threads) ----------------
__global__ __launch_bounds__(256) void pool_kernel(
    const float* __restrict__ h, const float* __restrict__ p,
    float* __restrict__ hp, int* __restrict__ map_out,
    int n_per, int k, float* __restrict__ z, int accumulate)
{
    __shared__ float ps[128];
    __shared__ float ss[256];
    __shared__ int   si[256];
    __shared__ float s_norm;
    __shared__ float rmax[2][128];
    __shared__ float rsum[2][128];
    const int b = blockIdx.x, tid = threadIdx.x;

    if (tid < 128) ps[tid] = p[tid];
    __syncthreads();
    if (tid < 32) {
        float v = ps[tid] * ps[tid] + ps[tid + 32] * ps[tid + 32]
                + ps[tid + 64] * ps[tid + 64] + ps[tid + 96] * ps[tid + 96];
#pragma unroll
        for (int o = 16; o; o >>= 1) v += __shfl_xor_sync(0xffffffffu, v, o);
        if (tid == 0) s_norm = __fsqrt_rn(v);
    }
    __syncthreads();

    const int warp = tid >> 5, lane = tid & 31;
    for (int i = warp; i < 256; i += 8) {
        if (i < n_per) {
            const float* row = h + ((size_t)b * n_per + i) * 128;
            float d = row[lane] * ps[lane] + row[lane + 32] * ps[lane + 32]
                    + row[lane + 64] * ps[lane + 64] + row[lane + 96] * ps[lane + 96];
#pragma unroll
            for (int o = 16; o; o >>= 1) d += __shfl_xor_sync(0xffffffffu, d, o);
            if (lane == 0) {
                ss[i] = xla_tanh(__fdiv_rn(d, s_norm));
                si[i] = i;
            }
        } else if (lane == 0) { ss[i] = -FLT_MAX_; si[i] = i; }
    }
    __syncthreads();

    // Bitonic sort 256 entries: (score desc, idx asc) to match lax.top_k
    for (int ksz = 2; ksz <= 256; ksz <<= 1) {
        for (int j = ksz >> 1; j > 0; j >>= 1) {
            int i = tid, ixj = i ^ j;
            if (ixj > i) {
                float s_i = ss[i], s_x = ss[ixj];
                int   i_i = si[i], i_x = si[ixj];
                bool before = (s_i > s_x) || (s_i == s_x && i_i < i_x);
                bool up = ((i & ksz) == 0);
                if (up ? !before : before) {
                    ss[i] = s_x; ss[ixj] = s_i;
                    si[i] = i_x; si[ixj] = i_i;
                }
            }
            __syncthreads();
        }
    }

    if (map_out) {
        for (int i = tid; i < n_per; i += 256) map_out[b * n_per + i] = -1;
        __syncthreads();
        for (int r = tid; r < k; r += 256) map_out[b * n_per + si[r]] = b * k + r;
    }

    // gather + scale + fused max/mean readout
    const int c = tid & 127, half = tid >> 7;
    float mymax = -FLT_MAX_, mysum = 0.f;
    for (int r = half; r < k; r += 2) {
        float v = __fmul_rn(h[((size_t)b * n_per + si[r]) * 128 + c], ss[r]);
        hp[((size_t)b * k + r) * 128 + c] = v;
        mymax = fmaxf(mymax, v);
        mysum = __fadd_rn(mysum, v);
    }
    rmax[half][c] = mymax; rsum[half][c] = mysum;
    __syncthreads();
    if (tid < 128) {
        float mx = fmaxf(rmax[0][tid], rmax[1][tid]);
        float sm = __fadd_rn(rsum[0][tid], rsum[1][tid]);
        float mean = __fdiv_rn(sm, (float)k);
        if (accumulate) {
            z[b * 256 + tid]       += mx;
            z[b * 256 + 128 + tid] += mean;
        } else {
            z[b * 256 + tid]       = mx;
            z[b * 256 + 128 + tid] = mean;
        }
    }
}

// ---------------- MLP head + log_softmax ----------------
__global__ __launch_bounds__(128) void mlp_kernel(
    const float* __restrict__ z,
    const float* __restrict__ wl1, const float* __restrict__ bl1,
    const float* __restrict__ wl2, const float* __restrict__ bl2,
    const float* __restrict__ wl3, const float* __restrict__ bl3,
    float* __restrict__ out)
{
    __shared__ float zr[256], t1[128], t2[64], lg[10];
    const int b = blockIdx.x, t = threadIdx.x;
    zr[t]       = z[b * 256 + t];
    zr[t + 128] = z[b * 256 + 128 + t];
    __syncthreads();
    float s = bl1[t];
    for (int k = 0; k < 256; k++) s = __fmaf_rn(zr[k], wl1[k * 128 + t], s);
    t1[t] = fmaxf(s, 0.f);
    __syncthreads();
    if (t < 64) {
        float s2 = bl2[t];
        for (int k = 0; k < 128; k++) s2 = __fmaf_rn(t1[k], wl2[k * 64 + t], s2);
        t2[t] = fmaxf(s2, 0.f);
    }
    __syncthreads();
    if (t < 10) {
        float s3 = bl3[t];
        for (int k = 0; k < 64; k++) s3 = __fmaf_rn(t2[k], wl3[k * 10 + t], s3);
        lg[t] = s3;
    }
    __syncthreads();
    if (t == 0) {
        float mx = -FLT_MAX_;
        for (int c = 0; c < 10; c++) mx = fmaxf(mx, lg[c]);
        double se = 0.0;
        for (int c = 0; c < 10; c++) se += exp((double)(lg[c] - mx));
        double lse = (double)mx + log(se);
        for (int c = 0; c < 10; c++) out[b * 10 + c] = (float)((double)lg[c] - lse);
    }
}

// ---------------- launch ----------------
extern "C" void kernel_launch(void* const* d_in, const int* in_sizes, int n_in,
                              void* d_out, int out_size)
{
    const float* x      = (const float*)d_in[0];
    const int*   src    = (const int*)  d_in[1];
    const int*   dst    = (const int*)  d_in[2];
    const float* w1_rel = (const float*)d_in[3];
    const float* w1_root= (const float*)d_in[4];
    const float* b1     = (const float*)d_in[5];
    const float* p1     = (const float*)d_in[6];
    const float* w2_rel = (const float*)d_in[7];
    const float* w2_root= (const float*)d_in[8];
    const float* b2     = (const float*)d_in[9];
    const float* p2     = (const float*)d_in[10];
    const float* w3_rel = (const float*)d_in[11];
    const float* w3_root= (const float*)d_in[12];
    const float* b3     = (const float*)d_in[13];
    const float* p3     = (const float*)d_in[14];
    const float* wl1    = (const float*)d_in[15];
    const float* bl1    = (const float*)d_in[16];
    const float* wl2    = (const float*)d_in[17];
    const float* bl2    = (const float*)d_in[18];
    const float* wl3    = (const float*)d_in[19];
    const float* bl3    = (const float*)d_in[20];
    float* out = (float*)d_out;

    float *agg, *h1, *hp1, *h2, *hp2, *h3, *hp3, *z;
    int *mapA, *mapB;
    cudaGetSymbolAddress((void**)&agg,  g_agg);
    cudaGetSymbolAddress((void**)&h1,   g_h1);
    cudaGetSymbolAddress((void**)&hp1,  g_hp1);
    cudaGetSymbolAddress((void**)&h2,   g_h2);
    cudaGetSymbolAddress((void**)&hp2,  g_hp2);
    cudaGetSymbolAddress((void**)&h3,   g_h3);
    cudaGetSymbolAddress((void**)&hp3,  g_hp3);
    cudaGetSymbolAddress((void**)&z,    g_z);
    cudaGetSymbolAddress((void**)&mapA, g_mapA);
    cudaGetSymbolAddress((void**)&mapB, g_mapB);

    // ---- layer 1 ----
    agg_kernel<<<BGR, 256>>>(x, src, dst, nullptr, nullptr, agg, NPG);
    gemm_conv<<<M1 / 64, 256>>>(agg, x, w1_rel, w1_root, b1, h1, M1);
    pool_kernel<<<BGR, 256>>>(h1, p1, hp1, mapA, NPG, K1, z, 0);

    // ---- layer 2 ----
    agg_kernel<<<BGR, 256>>>(hp1, src, dst, mapA, nullptr, agg, K1);
    gemm_conv<<<M2 / 64, 256>>>(agg, hp1, w2_rel, w2_root, b2, h2, M2);
    pool_kernel<<<BGR, 256>>>(h2, p2, hp2, mapB, K1, K2, z, 1);

    // ---- layer 3 ----
    agg_kernel<<<BGR, 256>>>(hp2, src, dst, mapA, mapB, agg, K2);
    gemm_conv<<<M3 / 64, 256>>>(agg, hp2, w3_rel, w3_root, b3, h3, M3);
    pool_kernel<<<BGR, 256>>>(h3, p3, hp3, nullptr, K2, K3, z, 1);

    // ---- head ----
    mlp_kernel<<<BGR, 128>>>(z, wl1, bl1, wl2, bl2, wl3, bl3, out);
}

// round 14
// speedup vs baseline: 1.3907x; 1.2753x over previous
#include <cuda_runtime.h>
#include <cstdint>

#define FLT_MAX_ 3.402823466e+38f

// Problem constants
#define BGR 512
#define NPG 256
#define EDG 1048576
#define EPG 2048          // edges per graph (edge array is grouped by graph)
#define HF  128
#define K1  205
#define K2  164
#define K3  132
#define M1  (BGR*NPG)   // 131072
#define M2  (BGR*K1)    // 104960
#define M3  (BGR*K2)    // 83968

// ---------------- XLA/Eigen fp32 tanh (generic_fast_tanh_float) ----------------
__device__ __forceinline__ float xla_tanh(float x) {
    const float ax = fabsf(x);
    float xc = fminf(fmaxf(x, -7.90531110763549805f), 7.90531110763549805f);
    float x2 = __fmul_rn(xc, xc);
    float p = __fmaf_rn(x2, -2.76076847742355e-16f, 2.00018790482477e-13f);
    p = __fmaf_rn(x2, p, -8.60467152213735e-11f);
    p = __fmaf_rn(x2, p,  5.12229709037114e-08f);
    p = __fmaf_rn(x2, p,  1.48572235717979e-05f);
    p = __fmaf_rn(x2, p,  6.37261928875436e-04f);
    p = __fmaf_rn(x2, p,  4.89352455891786e-03f);
    p = __fmul_rn(xc, p);
    float q = __fmaf_rn(x2, 1.19825839466702e-06f, 1.18534705686654e-04f);
    q = __fmaf_rn(x2, q, 2.26843463243900e-03f);
    q = __fmaf_rn(x2, q, 4.89352518554385e-03f);
    return (ax < 0.0004f) ? xc : __fdiv_rn(p, q);
}

// ---------------- scratch ----------------
__device__ __align__(16) float g_agg[M1 * HF];
__device__ __align__(16) float g_h1 [M1 * HF];
__device__ __align__(16) float g_hp1[M2 * HF];
__device__ __align__(16) float g_h2 [M2 * HF];
__device__ __align__(16) float g_hp2[M3 * HF];
__device__ __align__(16) float g_h3 [M3 * HF];
__device__ __align__(16) float g_hp3[BGR * K3 * HF];
__device__ int   g_mapA[M1];
__device__ int   g_mapB[M2];
__device__ __align__(16) float g_z[BGR * 2 * HF];

// ---------------- deterministic per-graph aggregation (exact fp32) ----------------
__global__ __launch_bounds__(256) void agg_kernel(
    const float* __restrict__ xin,
    const int* __restrict__ src, const int* __restrict__ dst,
    const int* __restrict__ map1, const int* __restrict__ map2,
    float* __restrict__ agg, int n_per)
{
    __shared__ int cnt[256];
    __shared__ int sc[256];
    __shared__ int offs[256];
    __shared__ int cur[256];
    __shared__ unsigned int elist[EPG];   // (e_local << 8) | s_local

    const int g = blockIdx.x, tid = threadIdx.x;
    cnt[tid] = 0;
    __syncthreads();

    int dl[8]; unsigned int pk[8];
#pragma unroll
    for (int i = 0; i < 8; i++) {
        const int el = tid + i * 256;
        const int e  = g * EPG + el;
        int s = __ldg(src + e);
        int d = __ldg(dst + e);
        bool ok = true;
        if (map1) { s = __ldg(map1 + s); d = __ldg(map1 + d); ok = ((s | d) >= 0); }
        if (ok && map2) { s = __ldg(map2 + s); d = __ldg(map2 + d); ok = ((s | d) >= 0); }
        if (ok) {
            const int dd = d - g * n_per;
            const int ss = s - g * n_per;
            dl[i] = dd;
            pk[i] = ((unsigned)el << 8) | (unsigned)ss;
            atomicAdd(&cnt[dd], 1);
        } else dl[i] = -1;
    }
    __syncthreads();

    sc[tid] = cnt[tid];
    __syncthreads();
    for (int st = 1; st < 256; st <<= 1) {
        int add = (tid >= st) ? sc[tid - st] : 0;
        __syncthreads();
        sc[tid] += add;
        __syncthreads();
    }
    offs[tid] = sc[tid] - cnt[tid];
    cur[tid]  = offs[tid];
    __syncthreads();

#pragma unroll
    for (int i = 0; i < 8; i++) {
        if (dl[i] >= 0) {
            int slot = atomicAdd(&cur[dl[i]], 1);
            elist[slot] = pk[i];
        }
    }
    __syncthreads();

    {
        const int beg = offs[tid], n = cnt[tid];
        for (int a = 1; a < n; a++) {
            unsigned int key = elist[beg + a];
            int b = a - 1;
            while (b >= 0 && elist[beg + b] > key) { elist[beg + b + 1] = elist[beg + b]; b--; }
            elist[beg + b + 1] = key;
        }
    }
    __syncthreads();

    const int warp = tid >> 5, lane = tid & 31;
    const float4* xg = reinterpret_cast<const float4*>(xin) + (size_t)g * n_per * 32;
    float4* av = reinterpret_cast<float4*>(agg) + (size_t)g * n_per * 32;
    for (int d = warp; d < n_per; d += 8) {
        const int beg = offs[d], n = cnt[d];
        float4 a = make_float4(0.f, 0.f, 0.f, 0.f);
        for (int j = 0; j < n; j++) {
            const int sl = (int)(elist[beg + j] & 255u);
            float4 v = __ldg(xg + (size_t)sl * 32 + lane);
            a.x += v.x; a.y += v.y; a.z += v.z; a.w += v.w;
        }
        av[(size_t)d * 32 + lane] = a;
    }
}

// ---------------- fused conv GEMM: out = relu((A1@B1 + bias) + A2@B2) ----------------
// 64x128 tile, 256 threads, 8Mx4N per thread, double-buffered smem.
// Kahan-compensated accumulation (16-term FFMA partials folded every 2 k-tiles):
// required accuracy class — plain sequential fp32 fails the top-k boundaries.
// __launch_bounds__(256,2): cap regs at 128 so TWO CTAs fit per SM (16 warps) —
// round-11 ran at 1 CTA/SM (12.5% occ) and sync/memory bubbles dominated.
__global__ __launch_bounds__(256, 2) void gemm_conv(
    const float* __restrict__ A1, const float* __restrict__ A2,
    const float* __restrict__ B1, const float* __restrict__ B2,
    const float* __restrict__ bias, float* __restrict__ out, int M)
{
    __shared__ float As[2][8][68];    // 68-pad: conflict-free transposed stores (272B row = 17*16B)
    __shared__ float Bs[2][8][128];
    const int tid = threadIdx.x;
    const int row0 = blockIdx.x * 64;
    const int tx = tid & 31;          // N: 4 cols each (tx*4)
    const int ty = tid >> 5;          // M: 8 rows each (ty*8)
    const int arow = tid >> 2;        // A load: row 0..63
    const int akp  = (tid & 3) * 2;   // A load: k pair
    const int bk   = tid >> 5;        // B load: k row 0..7
    const int bcol = (tid & 31) * 4;  // B load: col

    float acc[8][4], comp[8][4], part[8][4];
#pragma unroll
    for (int i = 0; i < 8; i++)
#pragma unroll
        for (int j = 0; j < 4; j++) { acc[i][j] = 0.f; comp[i][j] = 0.f; part[i][j] = 0.f; }

    // prefetch tile 0
    float2 pa = *reinterpret_cast<const float2*>(A1 + (size_t)(row0 + arow) * 128 + akp);
    float4 pb = *reinterpret_cast<const float4*>(B1 + (size_t)bk * 128 + bcol);
    As[0][akp][arow] = pa.x; As[0][akp + 1][arow] = pa.y;
    *reinterpret_cast<float4*>(&Bs[0][bk][bcol]) = pb;
    __syncthreads();

#pragma unroll 1
    for (int kk = 0; kk < 32; ++kk) {
        const int cur = kk & 1, nxt = cur ^ 1;
        if (kk < 31) {
            const int kn = kk + 1;
            const float* Asrc = (kn < 16) ? A1 : A2;
            const float* Bsrc = (kn < 16) ? B1 : B2;
            const int koff = (kn & 15) * 8;
            pa = *reinterpret_cast<const float2*>(Asrc + (size_t)(row0 + arow) * 128 + koff + akp);
            pb = *reinterpret_cast<const float4*>(Bsrc + (size_t)(koff + bk) * 128 + bcol);
        }
#pragma unroll
        for (int k = 0; k < 8; ++k) {
            float a[8], b[4];
            *reinterpret_cast<float4*>(a)     = *reinterpret_cast<const float4*>(&As[cur][k][ty * 8]);
            *reinterpret_cast<float4*>(a + 4) = *reinterpret_cast<const float4*>(&As[cur][k][ty * 8 + 4]);
            *reinterpret_cast<float4*>(b)     = *reinterpret_cast<const float4*>(&Bs[cur][k][tx * 4]);
#pragma unroll
            for (int i = 0; i < 8; i++)
#pragma unroll
                for (int j = 0; j < 4; j++) part[i][j] = __fmaf_rn(a[i], b[j], part[i][j]);
        }
        if (kk & 1) {
            // Kahan-fold 16-term partial into acc
#pragma unroll
            for (int i = 0; i < 8; i++)
#pragma unroll
                for (int j = 0; j < 4; j++) {
                    float y = __fsub_rn(part[i][j], comp[i][j]);
                    float t = __fadd_rn(acc[i][j], y);
                    comp[i][j] = __fsub_rn(__fsub_rn(t, acc[i][j]), y);
                    acc[i][j] = t;
                    part[i][j] = 0.f;
                }
            if (kk == 15) {
                // bias between the two K=128 halves (reference add order);
                // loaded here (not resident) to keep regs under the 2-CTA cap
#pragma unroll
                for (int j = 0; j < 4; j++) {
                    float bj = __ldg(bias + tx * 4 + j);
#pragma unroll
                    for (int i = 0; i < 8; i++) acc[i][j] = __fadd_rn(acc[i][j], bj);
                }
            }
        }
        if (kk < 31) {
            As[nxt][akp][arow] = pa.x; As[nxt][akp + 1][arow] = pa.y;
            *reinterpret_cast<float4*>(&Bs[nxt][bk][bcol]) = pb;
        }
        __syncthreads();
    }

#pragma unroll
    for (int i = 0; i < 8; i++) {
        const int m = row0 + ty * 8 + i;
        float4 o;
        o.x = fmaxf(__fsub_rn(acc[i][0], comp[i][0]), 0.f);
        o.y = fmaxf(__fsub_rn(acc[i][1], comp[i][1]), 0.f);
        o.z = fmaxf(__fsub_rn(acc[i][2], comp[i][2]), 0.f);
        o.w = fmaxf(__fsub_rn(acc[i][3], comp[i][3]), 0.f);
        *reinterpret_cast<float4*>(out + (size_t)m * 128 + tx * 4) = o;
    }
}

// ---------------- TopK pool + fused readout: per-graph block (256 threads) ----------------
__global__ __launch_bounds__(256) void pool_kernel(
    const float* __restrict__ h, const float* __restrict__ p,
    float* __restrict__ hp, int* __restrict__ map_out,
    int n_per, int k, float* __restrict__ z, int accumulate)
{
    __shared__ float ps[128];
    __shared__ float ss[256];
    __shared__ int   si[256];
    __shared__ float s_norm;
    __shared__ float rmax[2][128];
    __shared__ float rsum[2][128];
    const int b = blockIdx.x, tid = threadIdx.x;

    if (tid < 128) ps[tid] = p[tid];
    __syncthreads();
    if (tid < 32) {
        float v = ps[tid] * ps[tid] + ps[tid + 32] * ps[tid + 32]
                + ps[tid + 64] * ps[tid + 64] + ps[tid + 96] * ps[tid + 96];
#pragma unroll
        for (int o = 16; o; o >>= 1) v += __shfl_xor_sync(0xffffffffu, v, o);
        if (tid == 0) s_norm = __fsqrt_rn(v);
    }
    __syncthreads();

    const int warp = tid >> 5, lane = tid & 31;
    for (int i = warp; i < 256; i += 8) {
        if (i < n_per) {
            const float* row = h + ((size_t)b * n_per + i) * 128;
            float d = row[lane] * ps[lane] + row[lane + 32] * ps[lane + 32]
                    + row[lane + 64] * ps[lane + 64] + row[lane + 96] * ps[lane + 96];
#pragma unroll
            for (int o = 16; o; o >>= 1) d += __shfl_xor_sync(0xffffffffu, d, o);
            if (lane == 0) {
                ss[i] = xla_tanh(__fdiv_rn(d, s_norm));
                si[i] = i;
            }
        } else if (lane == 0) { ss[i] = -FLT_MAX_; si[i] = i; }
    }
    __syncthreads();

    // Bitonic sort 256 entries: (score desc, idx asc) to match lax.top_k
    for (int ksz = 2; ksz <= 256; ksz <<= 1) {
        for (int j = ksz >> 1; j > 0; j >>= 1) {
            int i = tid, ixj = i ^ j;
            if (ixj > i) {
                float s_i = ss[i], s_x = ss[ixj];
                int   i_i = si[i], i_x = si[ixj];
                bool before = (s_i > s_x) || (s_i == s_x && i_i < i_x);
                bool up = ((i & ksz) == 0);
                if (up ? !before : before) {
                    ss[i] = s_x; ss[ixj] = s_i;
                    si[i] = i_x; si[ixj] = i_i;
                }
            }
            __syncthreads();
        }
    }

    if (map_out) {
        for (int i = tid; i < n_per; i += 256) map_out[b * n_per + i] = -1;
        __syncthreads();
        for (int r = tid; r < k; r += 256) map_out[b * n_per + si[r]] = b * k + r;
    }

    // gather + scale + fused max/mean readout
    const int c = tid & 127, half = tid >> 7;
    float mymax = -FLT_MAX_, mysum = 0.f;
    for (int r = half; r < k; r += 2) {
        float v = __fmul_rn(h[((size_t)b * n_per + si[r]) * 128 + c], ss[r]);
        hp[((size_t)b * k + r) * 128 + c] = v;
        mymax = fmaxf(mymax, v);
        mysum = __fadd_rn(mysum, v);
    }
    rmax[half][c] = mymax; rsum[half][c] = mysum;
    __syncthreads();
    if (tid < 128) {
        float mx = fmaxf(rmax[0][tid], rmax[1][tid]);
        float sm = __fadd_rn(rsum[0][tid], rsum[1][tid]);
        float mean = __fdiv_rn(sm, (float)k);
        if (accumulate) {
            z[b * 256 + tid]       += mx;
            z[b * 256 + 128 + tid] += mean;
        } else {
            z[b * 256 + tid]       = mx;
            z[b * 256 + 128 + tid] = mean;
        }
    }
}

// ---------------- MLP head + log_softmax ----------------
__global__ __launch_bounds__(128) void mlp_kernel(
    const float* __restrict__ z,
    const float* __restrict__ wl1, const float* __restrict__ bl1,
    const float* __restrict__ wl2, const float* __restrict__ bl2,
    const float* __restrict__ wl3, const float* __restrict__ bl3,
    float* __restrict__ out)
{
    __shared__ float zr[256], t1[128], t2[64], lg[10];
    const int b = blockIdx.x, t = threadIdx.x;
    zr[t]       = z[b * 256 + t];
    zr[t + 128] = z[b * 256 + 128 + t];
    __syncthreads();
    float s = bl1[t];
    for (int k = 0; k < 256; k++) s = __fmaf_rn(zr[k], wl1[k * 128 + t], s);
    t1[t] = fmaxf(s, 0.f);
    __syncthreads();
    if (t < 64) {
        float s2 = bl2[t];
        for (int k = 0; k < 128; k++) s2 = __fmaf_rn(t1[k], wl2[k * 64 + t], s2);
        t2[t] = fmaxf(s2, 0.f);
    }
    __syncthreads();
    if (t < 10) {
        float s3 = bl3[t];
        for (int k = 0; k < 64; k++) s3 = __fmaf_rn(t2[k], wl3[k * 10 + t], s3);
        lg[t] = s3;
    }
    __syncthreads();
    if (t == 0) {
        float mx = -FLT_MAX_;
        for (int c = 0; c < 10; c++) mx = fmaxf(mx, lg[c]);
        double se = 0.0;
        for (int c = 0; c < 10; c++) se += exp((double)(lg[c] - mx));
        double lse = (double)mx + log(se);
        for (int c = 0; c < 10; c++) out[b * 10 + c] = (float)((double)lg[c] - lse);
    }
}

// ---------------- launch ----------------
extern "C" void kernel_launch(void* const* d_in, const int* in_sizes, int n_in,
                              void* d_out, int out_size)
{
    const float* x      = (const float*)d_in[0];
    const int*   src    = (const int*)  d_in[1];
    const int*   dst    = (const int*)  d_in[2];
    const float* w1_rel = (const float*)d_in[3];
    const float* w1_root= (const float*)d_in[4];
    const float* b1     = (const float*)d_in[5];
    const float* p1     = (const float*)d_in[6];
    const float* w2_rel = (const float*)d_in[7];
    const float* w2_root= (const float*)d_in[8];
    const float* b2     = (const float*)d_in[9];
    const float* p2     = (const float*)d_in[10];
    const float* w3_rel = (const float*)d_in[11];
    const float* w3_root= (const float*)d_in[12];
    const float* b3     = (const float*)d_in[13];
    const float* p3     = (const float*)d_in[14];
    const float* wl1    = (const float*)d_in[15];
    const float* bl1    = (const float*)d_in[16];
    const float* wl2    = (const float*)d_in[17];
    const float* bl2    = (const float*)d_in[18];
    const float* wl3    = (const float*)d_in[19];
    const float* bl3    = (const float*)d_in[20];
    float* out = (float*)d_out;

    float *agg, *h1, *hp1, *h2, *hp2, *h3, *hp3, *z;
    int *mapA, *mapB;
    cudaGetSymbolAddress((void**)&agg,  g_agg);
    cudaGetSymbolAddress((void**)&h1,   g_h1);
    cudaGetSymbolAddress((void**)&hp1,  g_hp1);
    cudaGetSymbolAddress((void**)&h2,   g_h2);
    cudaGetSymbolAddress((void**)&hp2,  g_hp2);
    cudaGetSymbolAddress((void**)&h3,   g_h3);
    cudaGetSymbolAddress((void**)&hp3,  g_hp3);
    cudaGetSymbolAddress((void**)&z,    g_z);
    cudaGetSymbolAddress((void**)&mapA, g_mapA);
    cudaGetSymbolAddress((void**)&mapB, g_mapB);

    // ---- layer 1 ----
    agg_kernel<<<BGR, 256>>>(x, src, dst, nullptr, nullptr, agg, NPG);
    gemm_conv<<<M1 / 64, 256>>>(agg, x, w1_rel, w1_root, b1, h1, M1);
    pool_kernel<<<BGR, 256>>>(h1, p1, hp1, mapA, NPG, K1, z, 0);

    // ---- layer 2 ----
    agg_kernel<<<BGR, 256>>>(hp1, src, dst, mapA, nullptr, agg, K1);
    gemm_conv<<<M2 / 64, 256>>>(agg, hp1, w2_rel, w2_root, b2, h2, M2);
    pool_kernel<<<BGR, 256>>>(h2, p2, hp2, mapB, K1, K2, z, 1);

    // ---- layer 3 ----
    agg_kernel<<<BGR, 256>>>(hp2, src, dst, mapA, mapB, agg, K2);
    gemm_conv<<<M3 / 64, 256>>>(agg, hp2, w3_rel, w3_root, b3, h3, M3);
    pool_kernel<<<BGR, 256>>>(h3, p3, hp3, nullptr, K2, K3, z, 1);

    // ---- head ----
    mlp_kernel<<<BGR, 128>>>(z, wl1, bl1, wl2, bl2, wl3, bl3, out);
}

// round 15
// speedup vs baseline: 1.5043x; 1.0817x over previous
#include <cuda_runtime.h>
#include <cstdint>

#define FLT_MAX_ 3.402823466e+38f

// Problem constants
#define BGR 512
#define NPG 256
#define EDG 1048576
#define EPG 2048          // edges per graph (edge array is grouped by graph)
#define HF  128
#define K1  205
#define K2  164
#define K3  132
#define M1  (BGR*NPG)   // 131072
#define M2  (BGR*K1)    // 104960
#define M3  (BGR*K2)    // 83968

typedef unsigned long long u64;

// ---- packed f32x2 helpers (Blackwell packed fp32; per-lane IEEE RN, bit-identical
//      to scalar __fmaf_rn/__fadd_rn/__fsub_rn applied element-wise) ----
__device__ __forceinline__ u64 pk2(float lo, float hi) {
    u64 r; asm("mov.b64 %0, {%1,%2};" : "=l"(r) : "f"(lo), "f"(hi)); return r;
}
__device__ __forceinline__ void upk2(u64 v, float& lo, float& hi) {
    asm("mov.b64 {%0,%1}, %2;" : "=f"(lo), "=f"(hi) : "l"(v));
}
__device__ __forceinline__ u64 fma2(u64 a, u64 b, u64 c) {
    u64 r; asm("fma.rn.f32x2 %0, %1, %2, %3;" : "=l"(r) : "l"(a), "l"(b), "l"(c)); return r;
}
__device__ __forceinline__ u64 add2(u64 a, u64 b) {
    u64 r; asm("add.rn.f32x2 %0, %1, %2;" : "=l"(r) : "l"(a), "l"(b)); return r;
}
__device__ __forceinline__ u64 sub2(u64 a, u64 b) {
    u64 r; asm("sub.rn.f32x2 %0, %1, %2;" : "=l"(r) : "l"(a), "l"(b)); return r;
}

// ---------------- XLA/Eigen fp32 tanh (generic_fast_tanh_float) ----------------
__device__ __forceinline__ float xla_tanh(float x) {
    const float ax = fabsf(x);
    float xc = fminf(fmaxf(x, -7.90531110763549805f), 7.90531110763549805f);
    float x2 = __fmul_rn(xc, xc);
    float p = __fmaf_rn(x2, -2.76076847742355e-16f, 2.00018790482477e-13f);
    p = __fmaf_rn(x2, p, -8.60467152213735e-11f);
    p = __fmaf_rn(x2, p,  5.12229709037114e-08f);
    p = __fmaf_rn(x2, p,  1.48572235717979e-05f);
    p = __fmaf_rn(x2, p,  6.37261928875436e-04f);
    p = __fmaf_rn(x2, p,  4.89352455891786e-03f);
    p = __fmul_rn(xc, p);
    float q = __fmaf_rn(x2, 1.19825839466702e-06f, 1.18534705686654e-04f);
    q = __fmaf_rn(x2, q, 2.26843463243900e-03f);
    q = __fmaf_rn(x2, q, 4.89352518554385e-03f);
    return (ax < 0.0004f) ? xc : __fdiv_rn(p, q);
}

// ---------------- scratch ----------------
__device__ __align__(16) float g_agg[M1 * HF];
__device__ __align__(16) float g_h1 [M1 * HF];
__device__ __align__(16) float g_hp1[M2 * HF];
__device__ __align__(16) float g_h2 [M2 * HF];
__device__ __align__(16) float g_hp2[M3 * HF];
__device__ __align__(16) float g_h3 [M3 * HF];
__device__ __align__(16) float g_hp3[BGR * K3 * HF];
__device__ int   g_mapA[M1];
__device__ int   g_mapB[M2];
__device__ __align__(16) float g_z[BGR * 2 * HF];

// ---------------- deterministic per-graph aggregation (exact fp32) ----------------
__global__ __launch_bounds__(256) void agg_kernel(
    const float* __restrict__ xin,
    const int* __restrict__ src, const int* __restrict__ dst,
    const int* __restrict__ map1, const int* __restrict__ map2,
    float* __restrict__ agg, int n_per)
{
    __shared__ int cnt[256];
    __shared__ int sc[256];
    __shared__ int offs[256];
    __shared__ int cur[256];
    __shared__ unsigned int elist[EPG];   // (e_local << 8) | s_local

    const int g = blockIdx.x, tid = threadIdx.x;
    cnt[tid] = 0;
    __syncthreads();

    int dl[8]; unsigned int pk[8];
#pragma unroll
    for (int i = 0; i < 8; i++) {
        const int el = tid + i * 256;
        const int e  = g * EPG + el;
        int s = __ldg(src + e);
        int d = __ldg(dst + e);
        bool ok = true;
        if (map1) { s = __ldg(map1 + s); d = __ldg(map1 + d); ok = ((s | d) >= 0); }
        if (ok && map2) { s = __ldg(map2 + s); d = __ldg(map2 + d); ok = ((s | d) >= 0); }
        if (ok) {
            const int dd = d - g * n_per;
            const int ss = s - g * n_per;
            dl[i] = dd;
            pk[i] = ((unsigned)el << 8) | (unsigned)ss;
            atomicAdd(&cnt[dd], 1);
        } else dl[i] = -1;
    }
    __syncthreads();

    sc[tid] = cnt[tid];
    __syncthreads();
    for (int st = 1; st < 256; st <<= 1) {
        int add = (tid >= st) ? sc[tid - st] : 0;
        __syncthreads();
        sc[tid] += add;
        __syncthreads();
    }
    offs[tid] = sc[tid] - cnt[tid];
    cur[tid]  = offs[tid];
    __syncthreads();

#pragma unroll
    for (int i = 0; i < 8; i++) {
        if (dl[i] >= 0) {
            int slot = atomicAdd(&cur[dl[i]], 1);
            elist[slot] = pk[i];
        }
    }
    __syncthreads();

    {
        const int beg = offs[tid], n = cnt[tid];
        for (int a = 1; a < n; a++) {
            unsigned int key = elist[beg + a];
            int b = a - 1;
            while (b >= 0 && elist[beg + b] > key) { elist[beg + b + 1] = elist[beg + b]; b--; }
            elist[beg + b + 1] = key;
        }
    }
    __syncthreads();

    const int warp = tid >> 5, lane = tid & 31;
    const float4* xg = reinterpret_cast<const float4*>(xin) + (size_t)g * n_per * 32;
    float4* av = reinterpret_cast<float4*>(agg) + (size_t)g * n_per * 32;
    for (int d = warp; d < n_per; d += 8) {
        const int beg = offs[d], n = cnt[d];
        float4 a = make_float4(0.f, 0.f, 0.f, 0.f);
        for (int j = 0; j < n; j++) {
            const int sl = (int)(elist[beg + j] & 255u);
            float4 v = __ldg(xg + (size_t)sl * 32 + lane);
            a.x += v.x; a.y += v.y; a.z += v.z; a.w += v.w;
        }
        av[(size_t)d * 32 + lane] = a;
    }
}

// ---------------- fused conv GEMM: out = relu((A1@B1 + bias) + A2@B2) ----------------
// 64x128 tile, 256 threads, 8Mx4N per thread, double-buffered smem, 2 CTAs/SM.
// Packed f32x2 FFMA2 inner loop (2 IEEE-RN fp32 FMAs per issue) with packed
// Kahan folds — per-lane math sequence identical to the scalar version, so the
// accuracy class (required: plain sequential fp32 fails top-k) is preserved.
__global__ __launch_bounds__(256, 2) void gemm_conv(
    const float* __restrict__ A1, const float* __restrict__ A2,
    const float* __restrict__ B1, const float* __restrict__ B2,
    const float* __restrict__ bias, float* __restrict__ out, int M)
{
    __shared__ float As[2][8][68];    // 68-pad: conflict-free transposed stores
    __shared__ float Bs[2][8][128];
    const int tid = threadIdx.x;
    const int row0 = blockIdx.x * 64;
    const int tx = tid & 31;          // N: 4 cols each (tx*4)
    const int ty = tid >> 5;          // M: 8 rows each (ty*8)
    const int arow = tid >> 2;        // A load: row 0..63
    const int akp  = (tid & 3) * 2;   // A load: k pair
    const int bk   = tid >> 5;        // B load: k row 0..7
    const int bcol = (tid & 31) * 4;  // B load: col

    u64 acc[8][2], comp[8][2], part[8][2];
#pragma unroll
    for (int i = 0; i < 8; i++)
#pragma unroll
        for (int j = 0; j < 2; j++) { acc[i][j] = 0ull; comp[i][j] = 0ull; part[i][j] = 0ull; }

    // prefetch tile 0
    float2 pa = *reinterpret_cast<const float2*>(A1 + (size_t)(row0 + arow) * 128 + akp);
    float4 pb = *reinterpret_cast<const float4*>(B1 + (size_t)bk * 128 + bcol);
    As[0][akp][arow] = pa.x; As[0][akp + 1][arow] = pa.y;
    *reinterpret_cast<float4*>(&Bs[0][bk][bcol]) = pb;
    __syncthreads();

#pragma unroll 1
    for (int kk = 0; kk < 32; ++kk) {
        const int cur = kk & 1, nxt = cur ^ 1;
        if (kk < 31) {
            const int kn = kk + 1;
            const float* Asrc = (kn < 16) ? A1 : A2;
            const float* Bsrc = (kn < 16) ? B1 : B2;
            const int koff = (kn & 15) * 8;
            pa = *reinterpret_cast<const float2*>(Asrc + (size_t)(row0 + arow) * 128 + koff + akp);
            pb = *reinterpret_cast<const float4*>(Bsrc + (size_t)(koff + bk) * 128 + bcol);
        }
#pragma unroll
        for (int k = 0; k < 8; ++k) {
            float a[8];
            *reinterpret_cast<float4*>(a)     = *reinterpret_cast<const float4*>(&As[cur][k][ty * 8]);
            *reinterpret_cast<float4*>(a + 4) = *reinterpret_cast<const float4*>(&As[cur][k][ty * 8 + 4]);
            float4 bv = *reinterpret_cast<const float4*>(&Bs[cur][k][tx * 4]);
            const u64 b0 = pk2(bv.x, bv.y);
            const u64 b1 = pk2(bv.z, bv.w);
#pragma unroll
            for (int i = 0; i < 8; i++) {
                const u64 ai = pk2(a[i], a[i]);
                part[i][0] = fma2(ai, b0, part[i][0]);
                part[i][1] = fma2(ai, b1, part[i][1]);
            }
        }
        if (kk & 1) {
            // packed Kahan-fold of 16-term partial into acc
#pragma unroll
            for (int i = 0; i < 8; i++)
#pragma unroll
                for (int j = 0; j < 2; j++) {
                    u64 y = sub2(part[i][j], comp[i][j]);
                    u64 t = add2(acc[i][j], y);
                    comp[i][j] = sub2(sub2(t, acc[i][j]), y);
                    acc[i][j] = t;
                    part[i][j] = 0ull;
                }
            if (kk == 15) {
                // bias between the two K=128 halves (reference add order)
                float4 b4 = __ldg(reinterpret_cast<const float4*>(bias + tx * 4));
                const u64 bb0 = pk2(b4.x, b4.y);
                const u64 bb1 = pk2(b4.z, b4.w);
#pragma unroll
                for (int i = 0; i < 8; i++) {
                    acc[i][0] = add2(acc[i][0], bb0);
                    acc[i][1] = add2(acc[i][1], bb1);
                }
            }
        }
        if (kk < 31) {
            As[nxt][akp][arow] = pa.x; As[nxt][akp + 1][arow] = pa.y;
            *reinterpret_cast<float4*>(&Bs[nxt][bk][bcol]) = pb;
        }
        __syncthreads();
    }

#pragma unroll
    for (int i = 0; i < 8; i++) {
        const int m = row0 + ty * 8 + i;
        u64 r0 = sub2(acc[i][0], comp[i][0]);
        u64 r1 = sub2(acc[i][1], comp[i][1]);
        float4 o;
        upk2(r0, o.x, o.y);
        upk2(r1, o.z, o.w);
        o.x = fmaxf(o.x, 0.f); o.y = fmaxf(o.y, 0.f);
        o.z = fmaxf(o.z, 0.f); o.w = fmaxf(o.w, 0.f);
        *reinterpret_cast<float4*>(out + (size_t)m * 128 + tx * 4) = o;
    }
}

// ---------------- TopK pool + fused readout: per-graph block (256 threads) ----------------
__global__ __launch_bounds__(256) void pool_kernel(
    const float* __restrict__ h, const float* __restrict__ p,
    float* __restrict__ hp, int* __restrict__ map_out,
    int n_per, int k, float* __restrict__ z, int accumulate)
{
    __shared__ float ps[128];
    __shared__ float ss[256];
    __shared__ int   si[256];
    __shared__ float s_norm;
    __shared__ float rmax[2][128];
    __shared__ float rsum[2][128];
    const int b = blockIdx.x, tid = threadIdx.x;

    if (tid < 128) ps[tid] = p[tid];
    __syncthreads();
    if (tid < 32) {
        float v = ps[tid] * ps[tid] + ps[tid + 32] * ps[tid + 32]
                + ps[tid + 64] * ps[tid + 64] + ps[tid + 96] * ps[tid + 96];
#pragma unroll
        for (int o = 16; o; o >>= 1) v += __shfl_xor_sync(0xffffffffu, v, o);
        if (tid == 0) s_norm = __fsqrt_rn(v);
    }
    __syncthreads();

    const int warp = tid >> 5, lane = tid & 31;
    for (int i = warp; i < 256; i += 8) {
        if (i < n_per) {
            const float* row = h + ((size_t)b * n_per + i) * 128;
            float d = row[lane] * ps[lane] + row[lane + 32] * ps[lane + 32]
                    + row[lane + 64] * ps[lane + 64] + row[lane + 96] * ps[lane + 96];
#pragma unroll
            for (int o = 16; o; o >>= 1) d += __shfl_xor_sync(0xffffffffu, d, o);
            if (lane == 0) {
                ss[i] = xla_tanh(__fdiv_rn(d, s_norm));
                si[i] = i;
            }
        } else if (lane == 0) { ss[i] = -FLT_MAX_; si[i] = i; }
    }
    __syncthreads();

    // Bitonic sort 256 entries: (score desc, idx asc) to match lax.top_k
    for (int ksz = 2; ksz <= 256; ksz <<= 1) {
        for (int j = ksz >> 1; j > 0; j >>= 1) {
            int i = tid, ixj = i ^ j;
            if (ixj > i) {
                float s_i = ss[i], s_x = ss[ixj];
                int   i_i = si[i], i_x = si[ixj];
                bool before = (s_i > s_x) || (s_i == s_x && i_i < i_x);
                bool up = ((i & ksz) == 0);
                if (up ? !before : before) {
                    ss[i] = s_x; ss[ixj] = s_i;
                    si[i] = i_x; si[ixj] = i_i;
                }
            }
            __syncthreads();
        }
    }

    if (map_out) {
        for (int i = tid; i < n_per; i += 256) map_out[b * n_per + i] = -1;
        __syncthreads();
        for (int r = tid; r < k; r += 256) map_out[b * n_per + si[r]] = b * k + r;
    }

    // gather + scale + fused max/mean readout
    const int c = tid & 127, half = tid >> 7;
    float mymax = -FLT_MAX_, mysum = 0.f;
    for (int r = half; r < k; r += 2) {
        float v = __fmul_rn(h[((size_t)b * n_per + si[r]) * 128 + c], ss[r]);
        hp[((size_t)b * k + r) * 128 + c] = v;
        mymax = fmaxf(mymax, v);
        mysum = __fadd_rn(mysum, v);
    }
    rmax[half][c] = mymax; rsum[half][c] = mysum;
    __syncthreads();
    if (tid < 128) {
        float mx = fmaxf(rmax[0][tid], rmax[1][tid]);
        float sm = __fadd_rn(rsum[0][tid], rsum[1][tid]);
        float mean = __fdiv_rn(sm, (float)k);
        if (accumulate) {
            z[b * 256 + tid]       += mx;
            z[b * 256 + 128 + tid] += mean;
        } else {
            z[b * 256 + tid]       = mx;
            z[b * 256 + 128 + tid] = mean;
        }
    }
}

// ---------------- MLP head + log_softmax ----------------
__global__ __launch_bounds__(128) void mlp_kernel(
    const float* __restrict__ z,
    const float* __restrict__ wl1, const float* __restrict__ bl1,
    const float* __restrict__ wl2, const float* __restrict__ bl2,
    const float* __restrict__ wl3, const float* __restrict__ bl3,
    float* __restrict__ out)
{
    __shared__ float zr[256], t1[128], t2[64], lg[10];
    const int b = blockIdx.x, t = threadIdx.x;
    zr[t]       = z[b * 256 + t];
    zr[t + 128] = z[b * 256 + 128 + t];
    __syncthreads();
    float s = bl1[t];
    for (int k = 0; k < 256; k++) s = __fmaf_rn(zr[k], wl1[k * 128 + t], s);
    t1[t] = fmaxf(s, 0.f);
    __syncthreads();
    if (t < 64) {
        float s2 = bl2[t];
        for (int k = 0; k < 128; k++) s2 = __fmaf_rn(t1[k], wl2[k * 64 + t], s2);
        t2[t] = fmaxf(s2, 0.f);
    }
    __syncthreads();
    if (t < 10) {
        float s3 = bl3[t];
        for (int k = 0; k < 64; k++) s3 = __fmaf_rn(t2[k], wl3[k * 10 + t], s3);
        lg[t] = s3;
    }
    __syncthreads();
    if (t == 0) {
        float mx = -FLT_MAX_;
        for (int c = 0; c < 10; c++) mx = fmaxf(mx, lg[c]);
        double se = 0.0;
        for (int c = 0; c < 10; c++) se += exp((double)(lg[c] - mx));
        double lse = (double)mx + log(se);
        for (int c = 0; c < 10; c++) out[b * 10 + c] = (float)((double)lg[c] - lse);
    }
}

// ---------------- launch ----------------
extern "C" void kernel_launch(void* const* d_in, const int* in_sizes, int n_in,
                              void* d_out, int out_size)
{
    const float* x      = (const float*)d_in[0];
    const int*   src    = (const int*)  d_in[1];
    const int*   dst    = (const int*)  d_in[2];
    const float* w1_rel = (const float*)d_in[3];
    const float* w1_root= (const float*)d_in[4];
    const float* b1     = (const float*)d_in[5];
    const float* p1     = (const float*)d_in[6];
    const float* w2_rel = (const float*)d_in[7];
    const float* w2_root= (const float*)d_in[8];
    const float* b2     = (const float*)d_in[9];
    const float* p2     = (const float*)d_in[10];
    const float* w3_rel = (const float*)d_in[11];
    const float* w3_root= (const float*)d_in[12];
    const float* b3     = (const float*)d_in[13];
    const float* p3     = (const float*)d_in[14];
    const float* wl1    = (const float*)d_in[15];
    const float* bl1    = (const float*)d_in[16];
    const float* wl2    = (const float*)d_in[17];
    const float* bl2    = (const float*)d_in[18];
    const float* wl3    = (const float*)d_in[19];
    const float* bl3    = (const float*)d_in[20];
    float* out = (float*)d_out;

    float *agg, *h1, *hp1, *h2, *hp2, *h3, *hp3, *z;
    int *mapA, *mapB;
    cudaGetSymbolAddress((void**)&agg,  g_agg);
    cudaGetSymbolAddress((void**)&h1,   g_h1);
    cudaGetSymbolAddress((void**)&hp1,  g_hp1);
    cudaGetSymbolAddress((void**)&h2,   g_h2);
    cudaGetSymbolAddress((void**)&hp2,  g_hp2);
    cudaGetSymbolAddress((void**)&h3,   g_h3);
    cudaGetSymbolAddress((void**)&hp3,  g_hp3);
    cudaGetSymbolAddress((void**)&z,    g_z);
    cudaGetSymbolAddress((void**)&mapA, g_mapA);
    cudaGetSymbolAddress((void**)&mapB, g_mapB);

    // ---- layer 1 ----
    agg_kernel<<<BGR, 256>>>(x, src, dst, nullptr, nullptr, agg, NPG);
    gemm_conv<<<M1 / 64, 256>>>(agg, x, w1_rel, w1_root, b1, h1, M1);
    pool_kernel<<<BGR, 256>>>(h1, p1, hp1, mapA, NPG, K1, z, 0);

    // ---- layer 2 ----
    agg_kernel<<<BGR, 256>>>(hp1, src, dst, mapA, nullptr, agg, K1);
    gemm_conv<<<M2 / 64, 256>>>(agg, hp1, w2_rel, w2_root, b2, h2, M2);
    pool_kernel<<<BGR, 256>>>(h2, p2, hp2, mapB, K1, K2, z, 1);

    // ---- layer 3 ----
    agg_kernel<<<BGR, 256>>>(hp2, src, dst, mapA, mapB, agg, K2);
    gemm_conv<<<M3 / 64, 256>>>(agg, hp2, w3_rel, w3_root, b3, h3, M3);
    pool_kernel<<<BGR, 256>>>(h3, p3, hp3, nullptr, K2, K3, z, 1);

    // ---- head ----
    mlp_kernel<<<BGR, 128>>>(z, wl1, bl1, wl2, bl2, wl3, bl3, out);
}

// round 17
// speedup vs baseline: 1.5156x; 1.0076x over previous
#include <cuda_runtime.h>
#include <cstdint>

#define FLT_MAX_ 3.402823466e+38f

// Problem constants
#define BGR 512
#define NPG 256
#define EDG 1048576
#define EPG 2048          // edges per graph (edge array is grouped by graph)
#define HF  128
#define K1  205
#define K2  164
#define K3  132
#define M1  (BGR*NPG)   // 131072
#define M2  (BGR*K1)    // 104960
#define M3  (BGR*K2)    // 83968

typedef unsigned long long u64;

// ---- packed f32x2 helpers (per-lane IEEE RN, bit-identical to scalar
//      __fmaf_rn/__fadd_rn/__fsub_rn applied element-wise) ----
__device__ __forceinline__ u64 pk2(float lo, float hi) {
    u64 r; asm("mov.b64 %0, {%1,%2};" : "=l"(r) : "f"(lo), "f"(hi)); return r;
}
__device__ __forceinline__ void upk2(u64 v, float& lo, float& hi) {
    asm("mov.b64 {%0,%1}, %2;" : "=f"(lo), "=f"(hi) : "l"(v));
}
__device__ __forceinline__ u64 fma2(u64 a, u64 b, u64 c) {
    u64 r; asm("fma.rn.f32x2 %0, %1, %2, %3;" : "=l"(r) : "l"(a), "l"(b), "l"(c)); return r;
}
__device__ __forceinline__ u64 add2(u64 a, u64 b) {
    u64 r; asm("add.rn.f32x2 %0, %1, %2;" : "=l"(r) : "l"(a), "l"(b)); return r;
}
__device__ __forceinline__ u64 sub2(u64 a, u64 b) {
    u64 r; asm("sub.rn.f32x2 %0, %1, %2;" : "=l"(r) : "l"(a), "l"(b)); return r;
}

// ---------------- XLA/Eigen fp32 tanh (generic_fast_tanh_float) ----------------
__device__ __forceinline__ float xla_tanh(float x) {
    const float ax = fabsf(x);
    float xc = fminf(fmaxf(x, -7.90531110763549805f), 7.90531110763549805f);
    float x2 = __fmul_rn(xc, xc);
    float p = __fmaf_rn(x2, -2.76076847742355e-16f, 2.00018790482477e-13f);
    p = __fmaf_rn(x2, p, -8.60467152213735e-11f);
    p = __fmaf_rn(x2, p,  5.12229709037114e-08f);
    p = __fmaf_rn(x2, p,  1.48572235717979e-05f);
    p = __fmaf_rn(x2, p,  6.37261928875436e-04f);
    p = __fmaf_rn(x2, p,  4.89352455891786e-03f);
    p = __fmul_rn(xc, p);
    float q = __fmaf_rn(x2, 1.19825839466702e-06f, 1.18534705686654e-04f);
    q = __fmaf_rn(x2, q, 2.26843463243900e-03f);
    q = __fmaf_rn(x2, q, 4.89352518554385e-03f);
    return (ax < 0.0004f) ? xc : __fdiv_rn(p, q);
}

// ---------------- scratch ----------------
__device__ __align__(16) float g_agg[M1 * HF];
__device__ __align__(16) float g_h1 [M1 * HF];
__device__ __align__(16) float g_hp1[M2 * HF];
__device__ __align__(16) float g_h2 [M2 * HF];
__device__ __align__(16) float g_hp2[M3 * HF];
__device__ __align__(16) float g_h3 [M3 * HF];
__device__ __align__(16) float g_hp3[BGR * K3 * HF];
__device__ int   g_mapA[M1];
__device__ int   g_mapB[M2];
__device__ __align__(16) float g_z[BGR * 2 * HF];

// ---------------- deterministic per-graph aggregation (exact fp32) ----------------
__global__ __launch_bounds__(256) void agg_kernel(
    const float* __restrict__ xin,
    const int* __restrict__ src, const int* __restrict__ dst,
    const int* __restrict__ map1, const int* __restrict__ map2,
    float* __restrict__ agg, int n_per)
{
    __shared__ int cnt[256];
    __shared__ int sc[256];
    __shared__ int offs[256];
    __shared__ int cur[256];
    __shared__ unsigned int elist[EPG];   // (e_local << 8) | s_local

    const int g = blockIdx.x, tid = threadIdx.x;
    cnt[tid] = 0;
    __syncthreads();

    int dl[8]; unsigned int pk[8];
#pragma unroll
    for (int i = 0; i < 8; i++) {
        const int el = tid + i * 256;
        const int e  = g * EPG + el;
        int s = __ldg(src + e);
        int d = __ldg(dst + e);
        bool ok = true;
        if (map1) { s = __ldg(map1 + s); d = __ldg(map1 + d); ok = ((s | d) >= 0); }
        if (ok && map2) { s = __ldg(map2 + s); d = __ldg(map2 + d); ok = ((s | d) >= 0); }
        if (ok) {
            const int dd = d - g * n_per;
            const int ss = s - g * n_per;
            dl[i] = dd;
            pk[i] = ((unsigned)el << 8) | (unsigned)ss;
            atomicAdd(&cnt[dd], 1);
        } else dl[i] = -1;
    }
    __syncthreads();

    sc[tid] = cnt[tid];
    __syncthreads();
    for (int st = 1; st < 256; st <<= 1) {
        int add = (tid >= st) ? sc[tid - st] : 0;
        __syncthreads();
        sc[tid] += add;
        __syncthreads();
    }
    offs[tid] = sc[tid] - cnt[tid];
    cur[tid]  = offs[tid];
    __syncthreads();

#pragma unroll
    for (int i = 0; i < 8; i++) {
        if (dl[i] >= 0) {
            int slot = atomicAdd(&cur[dl[i]], 1);
            elist[slot] = pk[i];
        }
    }
    __syncthreads();

    {
        const int beg = offs[tid], n = cnt[tid];
        for (int a = 1; a < n; a++) {
            unsigned int key = elist[beg + a];
            int b = a - 1;
            while (b >= 0 && elist[beg + b] > key) { elist[beg + b + 1] = elist[beg + b]; b--; }
            elist[beg + b + 1] = key;
        }
    }
    __syncthreads();

    const int warp = tid >> 5, lane = tid & 31;
    const float4* xg = reinterpret_cast<const float4*>(xin) + (size_t)g * n_per * 32;
    float4* av = reinterpret_cast<float4*>(agg) + (size_t)g * n_per * 32;
    for (int d = warp; d < n_per; d += 8) {
        const int beg = offs[d], n = cnt[d];
        float4 a = make_float4(0.f, 0.f, 0.f, 0.f);
        for (int j = 0; j < n; j++) {
            const int sl = (int)(elist[beg + j] & 255u);
            float4 v = __ldg(xg + (size_t)sl * 32 + lane);
            a.x += v.x; a.y += v.y; a.z += v.z; a.w += v.w;
        }
        av[(size_t)d * 32 + lane] = a;
    }
}

// ---------------- fused conv GEMM: out = relu((A1@B1 + bias) + A2@B2) ----------------
// 64x128 tile, 256 threads, 8Mx4N per thread as 4 M-PAIRS x 4 N, 2 CTAs/SM.
// M-paired FFMA2: A pairs load directly as u64 from transposed smem (zero packing);
// only B needs 4 splat-movs per k. Per-element FMA/Kahan order identical to the
// scalar version — accuracy class preserved (plain sequential fp32 fails top-k).
__global__ __launch_bounds__(256, 2) void gemm_conv(
    const float* __restrict__ A1, const float* __restrict__ A2,
    const float* __restrict__ B1, const float* __restrict__ B2,
    const float* __restrict__ bias, float* __restrict__ out, int M)
{
    __shared__ float As[2][8][68];    // transposed, 68-pad
    __shared__ float Bs[2][8][128];
    const int tid = threadIdx.x;
    const int row0 = blockIdx.x * 64;
    const int tx = tid & 31;          // N: 4 cols each (tx*4)
    const int ty = tid >> 5;          // M: 8 rows each (ty*8) = 4 pairs
    const int arow = tid >> 2;        // A load: row 0..63
    const int akp  = (tid & 3) * 2;   // A load: k pair
    const int bk   = tid >> 5;        // B load: k row 0..7
    const int bcol = (tid & 31) * 4;  // B load: col

    // acc[mp][n]: rows (ty*8+2mp, +1), col tx*4+n
    u64 acc[4][4], comp[4][4], part[4][4];
#pragma unroll
    for (int i = 0; i < 4; i++)
#pragma unroll
        for (int j = 0; j < 4; j++) { acc[i][j] = 0ull; comp[i][j] = 0ull; part[i][j] = 0ull; }

    // prefetch tile 0
    float2 pa = *reinterpret_cast<const float2*>(A1 + (size_t)(row0 + arow) * 128 + akp);
    float4 pb = *reinterpret_cast<const float4*>(B1 + (size_t)bk * 128 + bcol);
    As[0][akp][arow] = pa.x; As[0][akp + 1][arow] = pa.y;
    *reinterpret_cast<float4*>(&Bs[0][bk][bcol]) = pb;
    __syncthreads();

#pragma unroll 1
    for (int kk = 0; kk < 32; ++kk) {
        const int cur = kk & 1, nxt = cur ^ 1;
        if (kk < 31) {
            const int kn = kk + 1;
            const float* Asrc = (kn < 16) ? A1 : A2;
            const float* Bsrc = (kn < 16) ? B1 : B2;
            const int koff = (kn & 15) * 8;
            pa = *reinterpret_cast<const float2*>(Asrc + (size_t)(row0 + arow) * 128 + koff + akp);
            pb = *reinterpret_cast<const float4*>(Bsrc + (size_t)(koff + bk) * 128 + bcol);
        }
#pragma unroll
        for (int k = 0; k < 8; ++k) {
            // A pairs: direct u64 loads (adjacent M rows), broadcast across tx group
            ulonglong2 a01 = *reinterpret_cast<const ulonglong2*>(&As[cur][k][ty * 8]);
            ulonglong2 a23 = *reinterpret_cast<const ulonglong2*>(&As[cur][k][ty * 8 + 4]);
            const u64 ap[4] = { a01.x, a01.y, a23.x, a23.y };
            // B scalars: one LDS.128 + 4 splats
            float4 bv = *reinterpret_cast<const float4*>(&Bs[cur][k][tx * 4]);
            const u64 s0 = pk2(bv.x, bv.x);
            const u64 s1 = pk2(bv.y, bv.y);
            const u64 s2 = pk2(bv.z, bv.z);
            const u64 s3 = pk2(bv.w, bv.w);
#pragma unroll
            for (int i = 0; i < 4; i++) {
                part[i][0] = fma2(ap[i], s0, part[i][0]);
                part[i][1] = fma2(ap[i], s1, part[i][1]);
                part[i][2] = fma2(ap[i], s2, part[i][2]);
                part[i][3] = fma2(ap[i], s3, part[i][3]);
            }
        }
        if (kk & 1) {
            // packed Kahan-fold of 16-term partial into acc
#pragma unroll
            for (int i = 0; i < 4; i++)
#pragma unroll
                for (int j = 0; j < 4; j++) {
                    u64 y = sub2(part[i][j], comp[i][j]);
                    u64 t = add2(acc[i][j], y);
                    comp[i][j] = sub2(sub2(t, acc[i][j]), y);
                    acc[i][j] = t;
                    part[i][j] = 0ull;
                }
            if (kk == 15) {
                // bias between the two K=128 halves (reference add order)
                float4 b4 = __ldg(reinterpret_cast<const float4*>(bias + tx * 4));
                const u64 sb[4] = { pk2(b4.x, b4.x), pk2(b4.y, b4.y),
                                    pk2(b4.z, b4.z), pk2(b4.w, b4.w) };
#pragma unroll
                for (int i = 0; i < 4; i++)
#pragma unroll
                    for (int j = 0; j < 4; j++) acc[i][j] = add2(acc[i][j], sb[j]);
            }
        }
        if (kk < 31) {
            As[nxt][akp][arow] = pa.x; As[nxt][akp + 1][arow] = pa.y;
            *reinterpret_cast<float4*>(&Bs[nxt][bk][bcol]) = pb;
        }
        __syncthreads();
    }

#pragma unroll
    for (int i = 0; i < 4; i++) {
        const int m0 = row0 + ty * 8 + 2 * i;
        float4 o0, o1;
        u64 r0 = sub2(acc[i][0], comp[i][0]);
        u64 r1 = sub2(acc[i][1], comp[i][1]);
        u64 r2 = sub2(acc[i][2], comp[i][2]);
        u64 r3 = sub2(acc[i][3], comp[i][3]);
        upk2(r0, o0.x, o1.x);
        upk2(r1, o0.y, o1.y);
        upk2(r2, o0.z, o1.z);
        upk2(r3, o0.w, o1.w);
        o0.x = fmaxf(o0.x, 0.f); o0.y = fmaxf(o0.y, 0.f);
        o0.z = fmaxf(o0.z, 0.f); o0.w = fmaxf(o0.w, 0.f);
        o1.x = fmaxf(o1.x, 0.f); o1.y = fmaxf(o1.y, 0.f);
        o1.z = fmaxf(o1.z, 0.f); o1.w = fmaxf(o1.w, 0.f);
        *reinterpret_cast<float4*>(out + (size_t)m0 * 128 + tx * 4)       = o0;
        *reinterpret_cast<float4*>(out + (size_t)(m0 + 1) * 128 + tx * 4) = o1;
    }
}

// ---------------- TopK pool + fused readout: per-graph block (256 threads) ----------------
__global__ __launch_bounds__(256) void pool_kernel(
    const float* __restrict__ h, const float* __restrict__ p,
    float* __restrict__ hp, int* __restrict__ map_out,
    int n_per, int k, float* __restrict__ z, int accumulate)
{
    __shared__ float ps[128];
    __shared__ float ss[256];
    __shared__ int   si[256];
    __shared__ float s_norm;
    __shared__ float rmax[2][128];
    __shared__ float rsum[2][128];
    const int b = blockIdx.x, tid = threadIdx.x;

    if (tid < 128) ps[tid] = p[tid];
    __syncthreads();
    if (tid < 32) {
        float v = ps[tid] * ps[tid] + ps[tid + 32] * ps[tid + 32]
                + ps[tid + 64] * ps[tid + 64] + ps[tid + 96] * ps[tid + 96];
#pragma unroll
        for (int o = 16; o; o >>= 1) v += __shfl_xor_sync(0xffffffffu, v, o);
        if (tid == 0) s_norm = __fsqrt_rn(v);
    }
    __syncthreads();

    const int warp = tid >> 5, lane = tid & 31;
    for (int i = warp; i < 256; i += 8) {
        if (i < n_per) {
            const float* row = h + ((size_t)b * n_per + i) * 128;
            float d = row[lane] * ps[lane] + row[lane + 32] * ps[lane + 32]
                    + row[lane + 64] * ps[lane + 64] + row[lane + 96] * ps[lane + 96];
#pragma unroll
            for (int o = 16; o; o >>= 1) d += __shfl_xor_sync(0xffffffffu, d, o);
            if (lane == 0) {
                ss[i] = xla_tanh(__fdiv_rn(d, s_norm));
                si[i] = i;
            }
        } else if (lane == 0) { ss[i] = -FLT_MAX_; si[i] = i; }
    }
    __syncthreads();

    // Bitonic sort 256 entries: (score desc, idx asc) to match lax.top_k
    for (int ksz = 2; ksz <= 256; ksz <<= 1) {
        for (int j = ksz >> 1; j > 0; j >>= 1) {
            int i = tid, ixj = i ^ j;
            if (ixj > i) {
                float s_i = ss[i], s_x = ss[ixj];
                int   i_i = si[i], i_x = si[ixj];
                bool before = (s_i > s_x) || (s_i == s_x && i_i < i_x);
                bool up = ((i & ksz) == 0);
                if (up ? !before : before) {
                    ss[i] = s_x; ss[ixj] = s_i;
                    si[i] = i_x; si[ixj] = i_i;
                }
            }
            __syncthreads();
        }
    }

    if (map_out) {
        for (int i = tid; i < n_per; i += 256) map_out[b * n_per + i] = -1;
        __syncthreads();
        for (int r = tid; r < k; r += 256) map_out[b * n_per + si[r]] = b * k + r;
    }

    // gather + scale + fused max/mean readout
    const int c = tid & 127, half = tid >> 7;
    float mymax = -FLT_MAX_, mysum = 0.f;
    for (int r = half; r < k; r += 2) {
        float v = __fmul_rn(h[((size_t)b * n_per + si[r]) * 128 + c], ss[r]);
        hp[((size_t)b * k + r) * 128 + c] = v;
        mymax = fmaxf(mymax, v);
        mysum = __fadd_rn(mysum, v);
    }
    rmax[half][c] = mymax; rsum[half][c] = mysum;
    __syncthreads();
    if (tid < 128) {
        float mx = fmaxf(rmax[0][tid], rmax[1][tid]);
        float sm = __fadd_rn(rsum[0][tid], rsum[1][tid]);
        float mean = __fdiv_rn(sm, (float)k);
        if (accumulate) {
            z[b * 256 + tid]       += mx;
            z[b * 256 + 128 + tid] += mean;
        } else {
            z[b * 256 + tid]       = mx;
            z[b * 256 + 128 + tid] = mean;
        }
    }
}

// ---------------- MLP head + log_softmax ----------------
__global__ __launch_bounds__(128) void mlp_kernel(
    const float* __restrict__ z,
    const float* __restrict__ wl1, const float* __restrict__ bl1,
    const float* __restrict__ wl2, const float* __restrict__ bl2,
    const float* __restrict__ wl3, const float* __restrict__ bl3,
    float* __restrict__ out)
{
    __shared__ float zr[256], t1[128], t2[64], lg[10];
    const int b = blockIdx.x, t = threadIdx.x;
    zr[t]       = z[b * 256 + t];
    zr[t + 128] = z[b * 256 + 128 + t];
    __syncthreads();
    float s = bl1[t];
    for (int k = 0; k < 256; k++) s = __fmaf_rn(zr[k], wl1[k * 128 + t], s);
    t1[t] = fmaxf(s, 0.f);
    __syncthreads();
    if (t < 64) {
        float s2 = bl2[t];
        for (int k = 0; k < 128; k++) s2 = __fmaf_rn(t1[k], wl2[k * 64 + t], s2);
        t2[t] = fmaxf(s2, 0.f);
    }
    __syncthreads();
    if (t < 10) {
        float s3 = bl3[t];
        for (int k = 0; k < 64; k++) s3 = __fmaf_rn(t2[k], wl3[k * 10 + t], s3);
        lg[t] = s3;
    }
    __syncthreads();
    if (t == 0) {
        float mx = -FLT_MAX_;
        for (int c = 0; c < 10; c++) mx = fmaxf(mx, lg[c]);
        double se = 0.0;
        for (int c = 0; c < 10; c++) se += exp((double)(lg[c] - mx));
        double lse = (double)mx + log(se);
        for (int c = 0; c < 10; c++) out[b * 10 + c] = (float)((double)lg[c] - lse);
    }
}

// ---------------- launch ----------------
extern "C" void kernel_launch(void* const* d_in, const int* in_sizes, int n_in,
                              void* d_out, int out_size)
{
    const float* x      = (const float*)d_in[0];
    const int*   src    = (const int*)  d_in[1];
    const int*   dst    = (const int*)  d_in[2];
    const float* w1_rel = (const float*)d_in[3];
    const float* w1_root= (const float*)d_in[4];
    const float* b1     = (const float*)d_in[5];
    const float* p1     = (const float*)d_in[6];
    const float* w2_rel = (const float*)d_in[7];
    const float* w2_root= (const float*)d_in[8];
    const float* b2     = (const float*)d_in[9];
    const float* p2     = (const float*)d_in[10];
    const float* w3_rel = (const float*)d_in[11];
    const float* w3_root= (const float*)d_in[12];
    const float* b3     = (const float*)d_in[13];
    const float* p3     = (const float*)d_in[14];
    const float* wl1    = (const float*)d_in[15];
    const float* bl1    = (const float*)d_in[16];
    const float* wl2    = (const float*)d_in[17];
    const float* bl2    = (const float*)d_in[18];
    const float* wl3    = (const float*)d_in[19];
    const float* bl3    = (const float*)d_in[20];
    float* out = (float*)d_out;

    float *agg, *h1, *hp1, *h2, *hp2, *h3, *hp3, *z;
    int *mapA, *mapB;
    cudaGetSymbolAddress((void**)&agg,  g_agg);
    cudaGetSymbolAddress((void**)&h1,   g_h1);
    cudaGetSymbolAddress((void**)&hp1,  g_hp1);
    cudaGetSymbolAddress((void**)&h2,   g_h2);
    cudaGetSymbolAddress((void**)&hp2,  g_hp2);
    cudaGetSymbolAddress((void**)&h3,   g_h3);
    cudaGetSymbolAddress((void**)&hp3,  g_hp3);
    cudaGetSymbolAddress((void**)&z,    g_z);
    cudaGetSymbolAddress((void**)&mapA, g_mapA);
    cudaGetSymbolAddress((void**)&mapB, g_mapB);

    // ---- layer 1 ----
    agg_kernel<<<BGR, 256>>>(x, src, dst, nullptr, nullptr, agg, NPG);
    gemm_conv<<<M1 / 64, 256>>>(agg, x, w1_rel, w1_root, b1, h1, M1);
    pool_kernel<<<BGR, 256>>>(h1, p1, hp1, mapA, NPG, K1, z, 0);

    // ---- layer 2 ----
    agg_kernel<<<BGR, 256>>>(hp1, src, dst, mapA, nullptr, agg, K1);
    gemm_conv<<<M2 / 64, 256>>>(agg, hp1, w2_rel, w2_root, b2, h2, M2);
    pool_kernel<<<BGR, 256>>>(h2, p2, hp2, mapB, K1, K2, z, 1);

    // ---- layer 3 ----
    agg_kernel<<<BGR, 256>>>(hp2, src, dst, mapA, mapB, agg, K2);
    gemm_conv<<<M3 / 64, 256>>>(agg, hp2, w3_rel, w3_root, b3, h3, M3);
    pool_kernel<<<BGR, 256>>>(h3, p3, hp3, nullptr, K2, K3, z, 1);

    // ---- head ----
    mlp_kernel<<<BGR, 128>>>(z, wl1, bl1, wl2, bl2, wl3, bl3, out);
}